// round 11
// baseline (speedup 1.0000x reference)
#include <cuda_runtime.h>
#include <math.h>
#include <stdint.h>

#define N_NODES 50000
#define N_EDGES 800000
#define HEADS   8
#define ODIM    8
#define HDIM    64
#define CLAMP_V 5.0f
#define EPS_V   1e-8f
#define TILES   (N_EDGES / 32)      // 25000 tiles of 32 edges
#define EDGE_GRID 444               // 148 SMs * 3 persistent blocks

#define W_STRIDE   68               // sWT row stride in floats (272B, 16B-aligned)
#define EA_STRIDE  68               // sEA row stride (attrs, then scores)
#define KQV_STRIDE 192              // per-edge: K(64) Q(64) V(64)
#define SMEM_WT_FLOATS  (128 * W_STRIDE)     // 8704
#define SMEM_EA_FLOATS  (32 * EA_STRIDE)     // 2176
#define SMEM_KQV_FLOATS (32 * KQV_STRIDE)    // 6144
#define SMEM_EDGE_BYTES ((SMEM_WT_FLOATS + SMEM_EA_FLOATS + SMEM_KQV_FLOATS) * 4) // 68096

// ---------------- device scratch ----------------
__device__ __align__(16) float g_Qh[N_NODES * HDIM];
__device__ __align__(16) float g_Kh[N_NODES * HDIM];
__device__ __align__(16) float g_Vh[N_NODES * HDIM];
__device__ __align__(16) float g_den[N_NODES * HEADS];
__device__ __align__(16) float g_wV  [N_NODES * HDIM];
__device__ __align__(16) float g_rowV[N_NODES * HDIM];
__device__ unsigned g_orhigh;

// ---------------- helpers ----------------
__device__ __forceinline__ void redAddV4(float* p, float a, float b, float c, float d) {
    asm volatile("red.global.add.v4.f32 [%0], {%1,%2,%3,%4};"
                 :: "l"(p), "f"(a), "f"(b), "f"(c), "f"(d) : "memory");
}
__device__ __forceinline__ void redAdd1(float* p, float v) {
    asm volatile("red.global.add.f32 [%0], %1;" :: "l"(p), "f"(v) : "memory");
}
__device__ __forceinline__ void ffma2(unsigned long long& acc,
                                      unsigned long long a, unsigned long long b) {
    asm("fma.rn.f32x2 %0, %1, %2, %0;" : "+l"(acc) : "l"(a), "l"(b));
}
__device__ __forceinline__ unsigned long long pack2(float lo, float hi) {
    unsigned long long r;
    asm("mov.b64 %0, {%1,%2};" : "=l"(r) : "f"(lo), "f"(hi));
    return r;
}
__device__ __forceinline__ float sum2(unsigned long long v) {
    float2 r;
    asm("mov.b64 {%0,%1}, %2;" : "=f"(r.x), "=f"(r.y) : "l"(v));
    return r.x + r.y;
}
__device__ __forceinline__ float fsqrt_ap(float x) {
    float r; asm("sqrt.approx.f32 %0, %1;" : "=f"(r) : "f"(x)); return r;
}
__device__ __forceinline__ float signed_sqrt(float x) {
    return fsqrt_ap(fmaxf(x, 0.0f) + EPS_V) - fsqrt_ap(fmaxf(-x, 0.0f) + EPS_V);
}
__device__ __forceinline__ void cp_async16(uint32_t smem_addr, const void* gptr) {
    asm volatile("cp.async.cg.shared.global [%0], [%1], 16;"
                 :: "r"(smem_addr), "l"(gptr));
}
__device__ __forceinline__ void cp_commit() {
    asm volatile("cp.async.commit_group;" ::: "memory");
}
__device__ __forceinline__ void cp_wait1() {
    asm volatile("cp.async.wait_group 1;" ::: "memory");
}
__device__ __forceinline__ void cp_wait0() {
    asm volatile("cp.async.wait_group 0;" ::: "memory");
}
__device__ __forceinline__ void pair_bar(int id) {
    asm volatile("bar.sync %0, 64;" :: "r"(id) : "memory");
}

// ---------------- kernel 0: init accumulators + dtype flag ----------------
__global__ void k_init() {
    int i = blockIdx.x * blockDim.x + threadIdx.x;
    float4 z = make_float4(0.f, 0.f, 0.f, 0.f);
    if (i < N_NODES * HDIM / 4) {
        reinterpret_cast<float4*>(g_wV)[i] = z;
        reinterpret_cast<float4*>(g_rowV)[i] = z;
    }
    if (i < N_NODES * HEADS / 4) reinterpret_cast<float4*>(g_den)[i] = z;
    if (i == 0) g_orhigh = 0u;
}

// ---------------- kernel 1: index dtype detection ----------------
__global__ void k_detect(const unsigned* __restrict__ raw) {
    int i = blockIdx.x * blockDim.x + threadIdx.x;
    unsigned hi = (i < N_EDGES) ? raw[2 * i + 1] : 0u;
    hi = __reduce_or_sync(0xffffffffu, hi);
    if ((threadIdx.x & 31) == 0 && hi) atomicOr(&g_orhigh, hi);
}

// ---------------- kernel 2: node projections Q,K,V ----------------
__global__ void k_nodeproj(const float* __restrict__ x,
                           const float* __restrict__ Wq, const float* __restrict__ bq,
                           const float* __restrict__ Wk, const float* __restrict__ bk,
                           const float* __restrict__ Wv, const float* __restrict__ bv) {
    __shared__ float sW[64 * 64];
    __shared__ float sA[8][4][64];
    const int tid = threadIdx.x, warp = tid >> 5, lane = tid & 31;
    const int n0 = (blockIdx.x * 8 + warp) * 4;

    #pragma unroll
    for (int n = 0; n < 4; n++) {
        int node = n0 + n; if (node >= N_NODES) node = N_NODES - 1;
        sA[warp][n][lane]      = x[(size_t)node * 64 + lane];
        sA[warp][n][lane + 32] = x[(size_t)node * 64 + lane + 32];
    }

#define PROJ(W, B, OUT) do {                                                  \
    __syncthreads();                                                          \
    for (int i = tid; i < 4096; i += 256) sW[i] = (W)[i];                     \
    __syncthreads();                                                          \
    float b0 = (B)[lane], b1 = (B)[lane + 32];                                \
    float a0c0 = b0, a0c1 = b1, a1c0 = b0, a1c1 = b1;                         \
    float a2c0 = b0, a2c1 = b1, a3c0 = b0, a3c1 = b1;                         \
    _Pragma("unroll 16")                                                      \
    for (int k = 0; k < 64; k++) {                                            \
        float w0 = sW[k * 64 + lane], w1 = sW[k * 64 + lane + 32];            \
        float a0 = sA[warp][0][k], a1 = sA[warp][1][k];                       \
        float a2 = sA[warp][2][k], a3 = sA[warp][3][k];                       \
        a0c0 = fmaf(a0, w0, a0c0); a0c1 = fmaf(a0, w1, a0c1);                 \
        a1c0 = fmaf(a1, w0, a1c0); a1c1 = fmaf(a1, w1, a1c1);                 \
        a2c0 = fmaf(a2, w0, a2c0); a2c1 = fmaf(a2, w1, a2c1);                 \
        a3c0 = fmaf(a3, w0, a3c0); a3c1 = fmaf(a3, w1, a3c1);                 \
    }                                                                         \
    if (n0 + 0 < N_NODES) { (OUT)[(size_t)(n0+0)*64+lane]=a0c0; (OUT)[(size_t)(n0+0)*64+lane+32]=a0c1; } \
    if (n0 + 1 < N_NODES) { (OUT)[(size_t)(n0+1)*64+lane]=a1c0; (OUT)[(size_t)(n0+1)*64+lane+32]=a1c1; } \
    if (n0 + 2 < N_NODES) { (OUT)[(size_t)(n0+2)*64+lane]=a2c0; (OUT)[(size_t)(n0+2)*64+lane+32]=a2c1; } \
    if (n0 + 3 < N_NODES) { (OUT)[(size_t)(n0+3)*64+lane]=a3c0; (OUT)[(size_t)(n0+3)*64+lane+32]=a3c1; } \
} while (0)

    PROJ(Wq, bq, g_Qh);
    PROJ(Wk, bk, g_Kh);
    PROJ(Wv, bv, g_Vh);
#undef PROJ
}

// ---------------- kernel 3: fused edge kernel (warp-pair tiling) ----------------
// Warp pair (pair = warp>>1, sub = warp&1) shares 8 edges; lane owns score
// col j = sub*32+lane and only 2 weight rows (ew: cwj, eb: cwj+8).
// Per k4: 2 weight LDS.128 + 8 attr broadcasts for 32 FFMA2 = 0.5 wf/FFMA2
// (was 0.625) at unchanged occupancy 3. Pair syncs via named barriers.
__global__ void __launch_bounds__(256, 3)
k_edge(const float* __restrict__ edge_attr,
       const void* __restrict__ ei_raw,
       const float* __restrict__ We, const float* __restrict__ be,
       const float* __restrict__ Aw,
       float* __restrict__ wE_out) {
    extern __shared__ float smem[];
    float* sWT  = smem;                                   // [128][W_STRIDE]
    float* sEA  = smem + SMEM_WT_FLOATS;                  // [32][EA_STRIDE]
    float* sKQV = smem + SMEM_WT_FLOATS + SMEM_EA_FLOATS; // [32][KQV_STRIDE]
    __shared__ float sP[4][8][8];                         // exp(s) [pair][edge][head]

    const int tid = threadIdx.x, warp = tid >> 5, lane = tid & 31;
    const int pair = warp >> 1, sub = warp & 1;
    const int bar_id = pair + 1;                          // 0 reserved for syncthreads
    const int e_loc0 = pair * 8;

    // one-time: transpose We into sWT
    for (int i = tid; i < 128 * 64; i += 256) {
        int c = i & 127, k = i >> 7;
        sWT[c * W_STRIDE + k] = We[k * 128 + c];
    }
    __syncthreads();

    const int j  = sub * 32 + lane;                       // this lane's score col
    const int dj = j & 7, hj = j >> 3;                    // d, head for col j
    const int cwj = (hj << 4) + dj;                       // E_w GEMM col
    const float aw = Aw[dj * 8 + hj];

    const unsigned long long bini0 = pack2(be[cwj],     0.f);
    const unsigned long long bini1 = pack2(be[cwj + 8], 0.f);

    const float* wrow0 = &sWT[(cwj)     * W_STRIDE];
    const float* wrow1 = &sWT[(cwj + 8) * W_STRIDE];

    const bool idx64 = (g_orhigh == 0u);
    const long long* p64 = (const long long*)ei_raw;
    const int*       p32 = (const int*)ei_raw;

    const int l16 = lane & 15, lh = lane >> 4;            // half-warp split

    const uint32_t ea_smem = (uint32_t)__cvta_generic_to_shared(
        &sEA[e_loc0 * EA_STRIDE]);
    const uint32_t kqv_smem = (uint32_t)__cvta_generic_to_shared(
        &sKQV[e_loc0 * KQV_STRIDE]);

    for (int tile = blockIdx.x; tile < TILES; tile += gridDim.x) {
        const int e0 = tile * 32 + e_loc0;                // pair's first global edge

        // ---- indices (both warps load all 8 edges of the pair) ----
        int srcs[8], dsts[8];
        if (idx64) {
            #pragma unroll
            for (int n = 0; n < 8; n++) {
                srcs[n] = (int)__ldg(&p64[e0 + n]);
                dsts[n] = (int)__ldg(&p64[N_EDGES + e0 + n]);
            }
        } else {
            #pragma unroll
            for (int n = 0; n < 8; n++) {
                srcs[n] = __ldg(&p32[e0 + n]);
                dsts[n] = __ldg(&p32[N_EDGES + e0 + n]);
            }
        }

        // ---- group 0: edge attrs (pair-split: sub0 edges 0-3, sub1 4-7) ----
        #pragma unroll
        for (int m = 0; m < 2; m++) {
            int eloc = sub * 4 + 2 * m + lh;              // 0..7
            const float* ga = &edge_attr[(size_t)(e0 + eloc) * 64 + l16 * 4];
            cp_async16(ea_smem + (uint32_t)(eloc * EA_STRIDE + l16 * 4) * 4u, ga);
        }
        cp_commit();

        // ---- group 1: K (sub0) / Q (sub1), V split; covered by GEMM ----
        #pragma unroll
        for (int m = 0; m < 4; m++) {
            int eloc = 2 * m + lh;
            const float* s;
            if (sub == 0) {
                int sv = lh ? srcs[2 * m + 1] : srcs[2 * m];
                s = &g_Kh[(size_t)sv * 64 + l16 * 4];
                cp_async16(kqv_smem + (uint32_t)(eloc * KQV_STRIDE + l16 * 4) * 4u, s);
            } else {
                int dv = lh ? dsts[2 * m + 1] : dsts[2 * m];
                s = &g_Qh[(size_t)dv * 64 + l16 * 4];
                cp_async16(kqv_smem + (uint32_t)(eloc * KQV_STRIDE + 64 + l16 * 4) * 4u, s);
            }
        }
        #pragma unroll
        for (int m = 0; m < 2; m++) {
            int eloc = sub * 4 + 2 * m + lh;
            int sv = lh ? srcs[sub * 4 + 2 * m + 1] : srcs[sub * 4 + 2 * m];
            const float* s = &g_Vh[(size_t)sv * 64 + l16 * 4];
            cp_async16(kqv_smem + (uint32_t)(eloc * KQV_STRIDE + 128 + l16 * 4) * 4u, s);
        }
        cp_commit();

        cp_wait1();              // my attr chunk done
        pair_bar(bar_id);        // both warps' attrs visible

        // ---- GEMM: 8 edges x 2 cols/lane, FFMA2 (even-k, odd-k) lanes ----
        unsigned long long acc[8][2];
        #pragma unroll
        for (int e = 0; e < 8; e++) { acc[e][0] = bini0; acc[e][1] = bini1; }

        #pragma unroll 4
        for (int k4 = 0; k4 < 64; k4 += 4) {
            ulonglong2 ww0 = *reinterpret_cast<const ulonglong2*>(wrow0 + k4);
            ulonglong2 ww1 = *reinterpret_cast<const ulonglong2*>(wrow1 + k4);
            #pragma unroll
            for (int e = 0; e < 8; e++) {
                ulonglong2 aa = *reinterpret_cast<const ulonglong2*>(
                    &sEA[(e_loc0 + e) * EA_STRIDE + k4]);
                ffma2(acc[e][0], aa.x, ww0.x); ffma2(acc[e][0], aa.y, ww0.y);
                ffma2(acc[e][1], aa.x, ww1.x); ffma2(acc[e][1], aa.y, ww1.y);
            }
        }

        cp_wait0();              // my KQV chunk done
        pair_bar(bar_id);        // KQV visible; both warps past attr reads

        // ---- phase B: score for col j, wE (stcs), stash, per-head exp, den ----
        #pragma unroll
        for (int n = 0; n < 8; n++) {
            int e = e0 + n;
            int dst = dsts[n];
            const float* kqv = &sKQV[(e_loc0 + n) * KQV_STRIDE];
            float ew = sum2(acc[n][0]);
            float eb = sum2(acc[n][1]);

            float kq = kqv[j] + kqv[64 + j];
            float sc = signed_sqrt(kq * ew) + eb;

            __stcs(&wE_out[(size_t)e * 64 + j], sc);
            sEA[(e_loc0 + n) * EA_STRIDE + j] = sc;       // stash for phase C

            float p = sc * aw;
            #pragma unroll
            for (int off = 4; off > 0; off >>= 1)
                p += __shfl_xor_sync(0xffffffffu, p, off);
            p = __expf(fminf(fmaxf(p, -CLAMP_V), CLAMP_V));
            if (dj == 0) {
                sP[pair][n][hj] = p;
                redAdd1(&g_den[(size_t)dst * 8 + hj], p);
            }
        }
        pair_bar(bar_id);        // stash + sP visible to the pair

        // ---- phase C: numerator scatter (sub0 -> wV, sub1 -> rowV) ----
        const int q  = lane & 15;
        const int j0 = q * 4;
        const int hq = q >> 1;
        #pragma unroll
        for (int m = 0; m < 4; m++) {
            int eloc = 2 * m + lh;
            int dst = lh ? dsts[2 * m + 1] : dsts[2 * m];
            float p = sP[pair][eloc][hq];
            if (sub == 0) {
                float4 v = *reinterpret_cast<const float4*>(
                    &sKQV[(e_loc0 + eloc) * KQV_STRIDE + 128 + j0]);
                redAddV4(&g_wV[(size_t)dst * 64 + j0], v.x * p, v.y * p, v.z * p, v.w * p);
            } else {
                float4 et = *reinterpret_cast<const float4*>(
                    &sEA[(e_loc0 + eloc) * EA_STRIDE + j0]);
                redAddV4(&g_rowV[(size_t)dst * 64 + j0], et.x * p, et.y * p, et.z * p, et.w * p);
            }
        }
        pair_bar(bar_id);        // pair done with stash before next tile's cp
    }
}

// ---------------- kernel 4: finalize wV = (wV_raw + rowV_raw @ VeRow) / den ----
__global__ void k_final(const float* __restrict__ VeRow, float* __restrict__ wV_out) {
    int i = blockIdx.x * blockDim.x + threadIdx.x;
    if (i >= N_NODES * HDIM) return;
    int n = i >> 6, j = i & 63;
    int h = j >> 3, c = j & 7;
    float inv = 1.0f / (g_den[(size_t)n * 8 + h] + 1e-16f);
    float acc = g_wV[i];
    const float* rv = &g_rowV[(size_t)n * 64 + h * 8];
    #pragma unroll
    for (int d = 0; d < 8; d++)
        acc = fmaf(rv[d], __ldg(&VeRow[d * 64 + h * 8 + c]), acc);
    wV_out[i] = acc * inv;
}

// ---------------- launch ----------------
extern "C" void kernel_launch(void* const* d_in, const int* in_sizes, int n_in,
                              void* d_out, int out_size) {
    const float* x         = (const float*)d_in[0];
    const float* edge_attr = (const float*)d_in[1];
    const void*  ei_raw    = d_in[2];
    const float* Wq = (const float*)d_in[3];
    const float* bq = (const float*)d_in[4];
    const float* Wk = (const float*)d_in[5];
    const float* bk = (const float*)d_in[6];
    const float* We = (const float*)d_in[7];
    const float* be = (const float*)d_in[8];
    const float* Wv = (const float*)d_in[9];
    const float* bv = (const float*)d_in[10];
    const float* Aw = (const float*)d_in[11];
    const float* VeRow = (const float*)d_in[12];

    float* out    = (float*)d_out;
    float* wV_out = out;
    float* wE_out = out + (size_t)N_NODES * HDIM;

    cudaFuncSetAttribute(k_edge, cudaFuncAttributeMaxDynamicSharedMemorySize,
                         SMEM_EDGE_BYTES);

    k_init<<<(N_NODES * HDIM / 4 + 255) / 256, 256>>>();
    k_detect<<<(N_EDGES + 255) / 256, 256>>>((const unsigned*)ei_raw);
    k_nodeproj<<<(N_NODES + 31) / 32, 256>>>(x, Wq, bq, Wk, bk, Wv, bv);
    k_edge<<<EDGE_GRID, 256, SMEM_EDGE_BYTES>>>(edge_attr, ei_raw, We, be, Aw, wE_out);
    k_final<<<(N_NODES * HDIM + 255) / 256, 256>>>(VeRow, wV_out);
}

// round 12
// speedup vs baseline: 1.1088x; 1.1088x over previous
#include <cuda_runtime.h>
#include <math.h>
#include <stdint.h>

#define N_NODES 50000
#define N_EDGES 800000
#define HEADS   8
#define ODIM    8
#define HDIM    64
#define CLAMP_V 5.0f
#define EPS_V   1e-8f
#define TILES   (N_EDGES / 32)      // 25000 tiles of 32 edges
#define EDGE_GRID 444               // 148 SMs * 3 persistent blocks

#define W_STRIDE   68               // sWT row stride in floats (272B, 16B-aligned)
#define EA_STRIDE  68               // sEA row stride (attrs, then scores)
#define KQV_STRIDE 192              // per-edge: K(64) Q(64) V(64)
#define SMEM_WT_FLOATS  (128 * W_STRIDE)     // 8704
#define SMEM_EA_FLOATS  (32 * EA_STRIDE)     // 2176
#define SMEM_KQV_FLOATS (32 * KQV_STRIDE)    // 6144
#define SMEM_EDGE_BYTES ((SMEM_WT_FLOATS + SMEM_EA_FLOATS + SMEM_KQV_FLOATS) * 4) // 68096

// ---------------- device scratch ----------------
__device__ __align__(16) float g_Qh[N_NODES * HDIM];
__device__ __align__(16) float g_Kh[N_NODES * HDIM];
__device__ __align__(16) float g_Vh[N_NODES * HDIM];
__device__ __align__(16) float g_den[N_NODES * HEADS];
__device__ __align__(16) float g_wV  [N_NODES * HDIM];
__device__ __align__(16) float g_rowV[N_NODES * HDIM];
__device__ unsigned g_orhigh;

// ---------------- helpers ----------------
__device__ __forceinline__ void redAddV4(float* p, float a, float b, float c, float d) {
    asm volatile("red.global.add.v4.f32 [%0], {%1,%2,%3,%4};"
                 :: "l"(p), "f"(a), "f"(b), "f"(c), "f"(d) : "memory");
}
__device__ __forceinline__ void redAdd1(float* p, float v) {
    asm volatile("red.global.add.f32 [%0], %1;" :: "l"(p), "f"(v) : "memory");
}
__device__ __forceinline__ void ffma2(unsigned long long& acc,
                                      unsigned long long a, unsigned long long b) {
    asm("fma.rn.f32x2 %0, %1, %2, %0;" : "+l"(acc) : "l"(a), "l"(b));
}
__device__ __forceinline__ unsigned long long pack2(float lo, float hi) {
    unsigned long long r;
    asm("mov.b64 %0, {%1,%2};" : "=l"(r) : "f"(lo), "f"(hi));
    return r;
}
__device__ __forceinline__ float sum2(unsigned long long v) {
    float2 r;
    asm("mov.b64 {%0,%1}, %2;" : "=f"(r.x), "=f"(r.y) : "l"(v));
    return r.x + r.y;
}
__device__ __forceinline__ float fsqrt_ap(float x) {
    float r; asm("sqrt.approx.f32 %0, %1;" : "=f"(r) : "f"(x)); return r;
}
__device__ __forceinline__ float signed_sqrt(float x) {
    return fsqrt_ap(fmaxf(x, 0.0f) + EPS_V) - fsqrt_ap(fmaxf(-x, 0.0f) + EPS_V);
}
__device__ __forceinline__ void cp_async16(uint32_t smem_addr, const void* gptr) {
    asm volatile("cp.async.cg.shared.global [%0], [%1], 16;"
                 :: "r"(smem_addr), "l"(gptr));
}
// evict-first L2 policy for the big streaming edge_attr reads
__device__ __forceinline__ void cp_async16_stream(uint32_t smem_addr, const void* gptr) {
    asm volatile(
        "{\n\t"
        ".reg .b64 pol;\n\t"
        "createpolicy.fractional.L2::evict_first.b64 pol, 1.0;\n\t"
        "cp.async.cg.shared.global.L2::cache_hint [%0], [%1], 16, pol;\n\t"
        "}"
        :: "r"(smem_addr), "l"(gptr));
}
__device__ __forceinline__ void cp_commit() {
    asm volatile("cp.async.commit_group;" ::: "memory");
}
__device__ __forceinline__ void cp_wait1() {
    asm volatile("cp.async.wait_group 1;" ::: "memory");
}
__device__ __forceinline__ void cp_wait0() {
    asm volatile("cp.async.wait_group 0;" ::: "memory");
}

// ---------------- kernel 0: zero dtype flag (must precede detect's atomicOr) --
__global__ void k_flag() { g_orhigh = 0u; }

// ---------------- kernel 1: detect index dtype + zero accumulators ----------
// N_EDGES threads; N_EDGES == N_NODES*HDIM/4 so the same range covers zeroing.
__global__ void k_detect(const unsigned* __restrict__ raw) {
    int i = blockIdx.x * blockDim.x + threadIdx.x;
    float4 z = make_float4(0.f, 0.f, 0.f, 0.f);
    if (i < N_NODES * HDIM / 4) {
        reinterpret_cast<float4*>(g_wV)[i] = z;
        reinterpret_cast<float4*>(g_rowV)[i] = z;
    }
    if (i < N_NODES * HEADS / 4) reinterpret_cast<float4*>(g_den)[i] = z;
    unsigned hi = (i < N_EDGES) ? raw[2 * i + 1] : 0u;
    hi = __reduce_or_sync(0xffffffffu, hi);
    if ((threadIdx.x & 31) == 0 && hi) atomicOr(&g_orhigh, hi);
}

// ---------------- kernel 2: node projections Q,K,V (parallel over y) --------
__global__ void k_nodeproj(const float* __restrict__ x,
                           const float* __restrict__ Wq, const float* __restrict__ bq,
                           const float* __restrict__ Wk, const float* __restrict__ bk,
                           const float* __restrict__ Wv, const float* __restrict__ bv) {
    __shared__ float sW[64 * 64];
    __shared__ float sA[8][4][64];
    const int tid = threadIdx.x, warp = tid >> 5, lane = tid & 31;
    const int n0 = (blockIdx.x * 8 + warp) * 4;

    const float* W; const float* B; float* OUT;
    if (blockIdx.y == 0)      { W = Wq; B = bq; OUT = g_Qh; }
    else if (blockIdx.y == 1) { W = Wk; B = bk; OUT = g_Kh; }
    else                      { W = Wv; B = bv; OUT = g_Vh; }

    #pragma unroll
    for (int n = 0; n < 4; n++) {
        int node = n0 + n; if (node >= N_NODES) node = N_NODES - 1;
        sA[warp][n][lane]      = x[(size_t)node * 64 + lane];
        sA[warp][n][lane + 32] = x[(size_t)node * 64 + lane + 32];
    }
    for (int i = tid; i < 4096; i += 256) sW[i] = W[i];
    __syncthreads();

    float b0 = B[lane], b1 = B[lane + 32];
    float a0c0 = b0, a0c1 = b1, a1c0 = b0, a1c1 = b1;
    float a2c0 = b0, a2c1 = b1, a3c0 = b0, a3c1 = b1;
    #pragma unroll 16
    for (int k = 0; k < 64; k++) {
        float w0 = sW[k * 64 + lane], w1 = sW[k * 64 + lane + 32];
        float a0 = sA[warp][0][k], a1 = sA[warp][1][k];
        float a2 = sA[warp][2][k], a3 = sA[warp][3][k];
        a0c0 = fmaf(a0, w0, a0c0); a0c1 = fmaf(a0, w1, a0c1);
        a1c0 = fmaf(a1, w0, a1c0); a1c1 = fmaf(a1, w1, a1c1);
        a2c0 = fmaf(a2, w0, a2c0); a2c1 = fmaf(a2, w1, a2c1);
        a3c0 = fmaf(a3, w0, a3c0); a3c1 = fmaf(a3, w1, a3c1);
    }
    if (n0 + 0 < N_NODES) { OUT[(size_t)(n0+0)*64+lane]=a0c0; OUT[(size_t)(n0+0)*64+lane+32]=a0c1; }
    if (n0 + 1 < N_NODES) { OUT[(size_t)(n0+1)*64+lane]=a1c0; OUT[(size_t)(n0+1)*64+lane+32]=a1c1; }
    if (n0 + 2 < N_NODES) { OUT[(size_t)(n0+2)*64+lane]=a2c0; OUT[(size_t)(n0+2)*64+lane+32]=a2c1; }
    if (n0 + 3 < N_NODES) { OUT[(size_t)(n0+3)*64+lane]=a3c0; OUT[(size_t)(n0+3)*64+lane+32]=a3c1; }
}

// ---------------- kernel 3: fused edge kernel (R10 structure) ----------------
// ne=4, occ 3. Per tile: attrs (evict-first L2) + K/Q/V prefetched via 16B
// cp.async; KQV group waited only AFTER the GEMM. Phase C all-smem operands.
__global__ void __launch_bounds__(256, 3)
k_edge(const float* __restrict__ edge_attr,
       const void* __restrict__ ei_raw,
       const float* __restrict__ We, const float* __restrict__ be,
       const float* __restrict__ Aw,
       float* __restrict__ wE_out) {
    extern __shared__ float smem[];
    float* sWT  = smem;                                   // [128][W_STRIDE]
    float* sEA  = smem + SMEM_WT_FLOATS;                  // [32][EA_STRIDE]
    float* sKQV = smem + SMEM_WT_FLOATS + SMEM_EA_FLOATS; // [32][KQV_STRIDE]
    __shared__ float sP[8][4][8];                         // exp(s) [warp][edge][head]

    const int tid = threadIdx.x, warp = tid >> 5, lane = tid & 31;
    const int e_loc0 = warp * 4;

    for (int i = tid; i < 128 * 64; i += 256) {
        int c = i & 127, k = i >> 7;
        sWT[c * W_STRIDE + k] = We[k * 128 + c];
    }
    __syncthreads();

    const int d0 = lane & 7, h0 = lane >> 3;
    const int cw = (h0 << 4) + d0;
    const float aw0 = Aw[d0 * 8 + h0];
    const float aw1 = Aw[d0 * 8 + h0 + 4];

    const unsigned long long bini0 = pack2(be[cw],      0.f);
    const unsigned long long bini1 = pack2(be[cw + 8],  0.f);
    const unsigned long long bini2 = pack2(be[cw + 64], 0.f);
    const unsigned long long bini3 = pack2(be[cw + 72], 0.f);

    const float* wrow0 = &sWT[(cw)      * W_STRIDE];
    const float* wrow1 = &sWT[(cw + 8)  * W_STRIDE];
    const float* wrow2 = &sWT[(cw + 64) * W_STRIDE];
    const float* wrow3 = &sWT[(cw + 72) * W_STRIDE];

    const bool idx64 = (g_orhigh == 0u);
    const long long* p64 = (const long long*)ei_raw;
    const int*       p32 = (const int*)ei_raw;

    const int l16 = lane & 15, lh = lane >> 4;

    const uint32_t ea_smem = (uint32_t)__cvta_generic_to_shared(
        &sEA[e_loc0 * EA_STRIDE]);
    const uint32_t kqv_smem = (uint32_t)__cvta_generic_to_shared(
        &sKQV[e_loc0 * KQV_STRIDE]);

    for (int tile = blockIdx.x; tile < TILES; tile += gridDim.x) {
        const int e0 = tile * 32 + e_loc0;

        int srcs[4], dsts[4];
        if (idx64) {
            #pragma unroll
            for (int n = 0; n < 4; n++) {
                srcs[n] = (int)__ldg(&p64[e0 + n]);
                dsts[n] = (int)__ldg(&p64[N_EDGES + e0 + n]);
            }
        } else {
            #pragma unroll
            for (int n = 0; n < 4; n++) {
                srcs[n] = __ldg(&p32[e0 + n]);
                dsts[n] = __ldg(&p32[N_EDGES + e0 + n]);
            }
        }

        // group 0: edge attrs (streaming, evict-first L2)
        #pragma unroll
        for (int m = 0; m < 2; m++) {
            const float* ga = &edge_attr[(size_t)(e0 + 2 * m + lh) * 64 + l16 * 4];
            cp_async16_stream(ea_smem + (uint32_t)((2 * m + lh) * EA_STRIDE + l16 * 4) * 4u, ga);
        }
        cp_commit();

        // group 1: K/Q (4x cp16) + V (2x cp16), covered by GEMM
        #pragma unroll
        for (int n = 0; n < 4; n++) {
            const float* s = (lh == 0)
                ? &g_Kh[(size_t)srcs[n] * 64 + l16 * 4]
                : &g_Qh[(size_t)dsts[n] * 64 + l16 * 4];
            cp_async16(kqv_smem + (uint32_t)(n * KQV_STRIDE + lh * 64 + l16 * 4) * 4u, s);
        }
        #pragma unroll
        for (int m = 0; m < 2; m++) {
            int sv = (lh == 0) ? srcs[2 * m] : srcs[2 * m + 1];
            const float* s = &g_Vh[(size_t)sv * 64 + l16 * 4];
            cp_async16(kqv_smem + (uint32_t)((2 * m + lh) * KQV_STRIDE + 128 + l16 * 4) * 4u, s);
        }
        cp_commit();

        cp_wait1();
        __syncwarp();

        // GEMM: 4 edges x 4 cols, FFMA2 (even-k, odd-k) lanes
        unsigned long long acc[4][4];
        #pragma unroll
        for (int e = 0; e < 4; e++) {
            acc[e][0] = bini0; acc[e][1] = bini1;
            acc[e][2] = bini2; acc[e][3] = bini3;
        }

        #pragma unroll 4
        for (int k4 = 0; k4 < 64; k4 += 4) {
            ulonglong2 ww0 = *reinterpret_cast<const ulonglong2*>(wrow0 + k4);
            ulonglong2 ww1 = *reinterpret_cast<const ulonglong2*>(wrow1 + k4);
            ulonglong2 ww2 = *reinterpret_cast<const ulonglong2*>(wrow2 + k4);
            ulonglong2 ww3 = *reinterpret_cast<const ulonglong2*>(wrow3 + k4);
            #pragma unroll
            for (int e = 0; e < 4; e++) {
                ulonglong2 aa = *reinterpret_cast<const ulonglong2*>(
                    &sEA[(e_loc0 + e) * EA_STRIDE + k4]);
                ffma2(acc[e][0], aa.x, ww0.x); ffma2(acc[e][0], aa.y, ww0.y);
                ffma2(acc[e][1], aa.x, ww1.x); ffma2(acc[e][1], aa.y, ww1.y);
                ffma2(acc[e][2], aa.x, ww2.x); ffma2(acc[e][2], aa.y, ww2.y);
                ffma2(acc[e][3], aa.x, ww3.x); ffma2(acc[e][3], aa.y, ww3.y);
            }
        }

        cp_wait0();
        __syncwarp();

        // phase B: scores (stcs + smem stash), per-head exp, den red
        #pragma unroll
        for (int n = 0; n < 4; n++) {
            int e = e0 + n;
            int dst = dsts[n];
            const float* kqv = &sKQV[(e_loc0 + n) * KQV_STRIDE];
            float ew0 = sum2(acc[n][0]);
            float eb0 = sum2(acc[n][1]);
            float ew1 = sum2(acc[n][2]);
            float eb1 = sum2(acc[n][3]);

            float kq0 = kqv[lane]      + kqv[lane + 64];
            float kq1 = kqv[lane + 32] + kqv[lane + 96];
            float sc0 = signed_sqrt(kq0 * ew0) + eb0;
            float sc1 = signed_sqrt(kq1 * ew1) + eb1;

            __stcs(&wE_out[(size_t)e * 64 + lane],      sc0);
            __stcs(&wE_out[(size_t)e * 64 + lane + 32], sc1);
            float* srow = &sEA[(e_loc0 + n) * EA_STRIDE];
            srow[lane]      = sc0;
            srow[lane + 32] = sc1;

            float p0 = sc0 * aw0;
            float p1 = sc1 * aw1;
            #pragma unroll
            for (int off = 4; off > 0; off >>= 1) {
                p0 += __shfl_xor_sync(0xffffffffu, p0, off);
                p1 += __shfl_xor_sync(0xffffffffu, p1, off);
            }
            p0 = __expf(fminf(fmaxf(p0, -CLAMP_V), CLAMP_V));
            p1 = __expf(fminf(fmaxf(p1, -CLAMP_V), CLAMP_V));
            if (d0 == 0) {
                sP[warp][n][h0]     = p0;
                sP[warp][n][h0 + 4] = p1;
                redAdd1(&g_den[(size_t)dst * 8 + h0],     p0);
                redAdd1(&g_den[(size_t)dst * 8 + h0 + 4], p1);
            }
        }
        __syncwarp();

        // phase C: numerator scatter (all operands in smem)
        const int q  = lane & 15;
        const int j0 = q * 4;
        const int hq = q >> 1;
        #pragma unroll
        for (int n = 0; n < 4; n++) {
            float p = sP[warp][n][hq];
            int dst = dsts[n];
            if (lane < 16) {
                float4 v = *reinterpret_cast<const float4*>(
                    &sKQV[(e_loc0 + n) * KQV_STRIDE + 128 + j0]);
                redAddV4(&g_wV[(size_t)dst * 64 + j0], v.x * p, v.y * p, v.z * p, v.w * p);
            } else {
                float4 et = *reinterpret_cast<const float4*>(
                    &sEA[(e_loc0 + n) * EA_STRIDE + j0]);
                redAddV4(&g_rowV[(size_t)dst * 64 + j0], et.x * p, et.y * p, et.z * p, et.w * p);
            }
        }
        __syncwarp();
    }
}

// ---------------- kernel 4: finalize wV = (wV_raw + rowV_raw @ VeRow) / den ----
__global__ void k_final(const float* __restrict__ VeRow, float* __restrict__ wV_out) {
    int i = blockIdx.x * blockDim.x + threadIdx.x;
    if (i >= N_NODES * HDIM) return;
    int n = i >> 6, j = i & 63;
    int h = j >> 3, c = j & 7;
    float inv = 1.0f / (g_den[(size_t)n * 8 + h] + 1e-16f);
    float acc = g_wV[i];
    const float* rv = &g_rowV[(size_t)n * 64 + h * 8];
    #pragma unroll
    for (int d = 0; d < 8; d++)
        acc = fmaf(rv[d], __ldg(&VeRow[d * 64 + h * 8 + c]), acc);
    wV_out[i] = acc * inv;
}

// ---------------- launch ----------------
extern "C" void kernel_launch(void* const* d_in, const int* in_sizes, int n_in,
                              void* d_out, int out_size) {
    const float* x         = (const float*)d_in[0];
    const float* edge_attr = (const float*)d_in[1];
    const void*  ei_raw    = d_in[2];
    const float* Wq = (const float*)d_in[3];
    const float* bq = (const float*)d_in[4];
    const float* Wk = (const float*)d_in[5];
    const float* bk = (const float*)d_in[6];
    const float* We = (const float*)d_in[7];
    const float* be = (const float*)d_in[8];
    const float* Wv = (const float*)d_in[9];
    const float* bv = (const float*)d_in[10];
    const float* Aw = (const float*)d_in[11];
    const float* VeRow = (const float*)d_in[12];

    float* out    = (float*)d_out;
    float* wV_out = out;
    float* wE_out = out + (size_t)N_NODES * HDIM;

    cudaFuncSetAttribute(k_edge, cudaFuncAttributeMaxDynamicSharedMemorySize,
                         SMEM_EDGE_BYTES);

    k_flag<<<1, 1>>>();
    k_detect<<<(N_EDGES + 255) / 256, 256>>>((const unsigned*)ei_raw);
    dim3 npgrid((N_NODES + 31) / 32, 3);
    k_nodeproj<<<npgrid, 256>>>(x, Wq, bq, Wk, bk, Wv, bv);
    k_edge<<<EDGE_GRID, 256, SMEM_EDGE_BYTES>>>(edge_attr, ei_raw, We, be, Aw, wE_out);
    k_final<<<(N_NODES * HDIM + 255) / 256, 256>>>(VeRow, wV_out);
}

// round 13
// speedup vs baseline: 1.1341x; 1.0228x over previous
#include <cuda_runtime.h>
#include <math.h>
#include <stdint.h>

#define N_NODES 50000
#define N_EDGES 800000
#define HEADS   8
#define ODIM    8
#define HDIM    64
#define CLAMP_V 5.0f
#define EPS_V   1e-8f
#define SQRT_EPS 9.9999997e-05f     // fp32 sqrt(1e-8)
#define TILES   (N_EDGES / 32)      // 25000 tiles of 32 edges
#define EDGE_GRID 444               // 148 SMs * 3 persistent blocks

#define W_STRIDE   68               // sWT row stride in floats (272B, 16B-aligned)
#define EA_STRIDE  68               // sEA row stride (attrs, then scores)
#define KQV_STRIDE 192              // per-edge: K(64) Q(64) V(64)
#define SMEM_WT_FLOATS  (128 * W_STRIDE)     // 8704
#define SMEM_EA_FLOATS  (32 * EA_STRIDE)     // 2176
#define SMEM_KQV_FLOATS (32 * KQV_STRIDE)    // 6144
#define SMEM_EDGE_BYTES ((SMEM_WT_FLOATS + SMEM_EA_FLOATS + SMEM_KQV_FLOATS) * 4) // 68096

// ---------------- device scratch ----------------
__device__ __align__(16) float g_Qh[N_NODES * HDIM];
__device__ __align__(16) float g_Kh[N_NODES * HDIM];
__device__ __align__(16) float g_Vh[N_NODES * HDIM];
__device__ __align__(16) float g_den[N_NODES * HEADS];
__device__ __align__(16) float g_wV  [N_NODES * HDIM];
__device__ __align__(16) float g_rowV[N_NODES * HDIM];
__device__ unsigned g_orhigh;

// ---------------- helpers ----------------
__device__ __forceinline__ void redAddV4(float* p, float a, float b, float c, float d) {
    asm volatile("red.global.add.v4.f32 [%0], {%1,%2,%3,%4};"
                 :: "l"(p), "f"(a), "f"(b), "f"(c), "f"(d) : "memory");
}
__device__ __forceinline__ void redAdd1(float* p, float v) {
    asm volatile("red.global.add.f32 [%0], %1;" :: "l"(p), "f"(v) : "memory");
}
__device__ __forceinline__ void ffma2(unsigned long long& acc,
                                      unsigned long long a, unsigned long long b) {
    asm("fma.rn.f32x2 %0, %1, %2, %0;" : "+l"(acc) : "l"(a), "l"(b));
}
__device__ __forceinline__ unsigned long long pack2(float lo, float hi) {
    unsigned long long r;
    asm("mov.b64 %0, {%1,%2};" : "=l"(r) : "f"(lo), "f"(hi));
    return r;
}
__device__ __forceinline__ float sum2(unsigned long long v) {
    float2 r;
    asm("mov.b64 {%0,%1}, %2;" : "=f"(r.x), "=f"(r.y) : "l"(v));
    return r.x + r.y;
}
__device__ __forceinline__ float fsqrt_ap(float x) {
    float r; asm("sqrt.approx.f32 %0, %1;" : "=f"(r) : "f"(x)); return r;
}
// sqrt(relu(x)+eps) - sqrt(relu(-x)+eps) == copysign(sqrt(|x|+eps)-sqrt(eps), x)
__device__ __forceinline__ float signed_sqrt(float x) {
    float t = fsqrt_ap(fabsf(x) + EPS_V) - SQRT_EPS;
    return copysignf(t, x);
}
__device__ __forceinline__ void cp_async16(uint32_t smem_addr, const void* gptr) {
    asm volatile("cp.async.cg.shared.global [%0], [%1], 16;"
                 :: "r"(smem_addr), "l"(gptr));
}
// evict-first L2 policy for the big streaming edge_attr reads
__device__ __forceinline__ void cp_async16_stream(uint32_t smem_addr, const void* gptr) {
    asm volatile(
        "{\n\t"
        ".reg .b64 pol;\n\t"
        "createpolicy.fractional.L2::evict_first.b64 pol, 1.0;\n\t"
        "cp.async.cg.shared.global.L2::cache_hint [%0], [%1], 16, pol;\n\t"
        "}"
        :: "r"(smem_addr), "l"(gptr));
}
__device__ __forceinline__ void cp_commit() {
    asm volatile("cp.async.commit_group;" ::: "memory");
}
__device__ __forceinline__ void cp_wait1() {
    asm volatile("cp.async.wait_group 1;" ::: "memory");
}
__device__ __forceinline__ void cp_wait0() {
    asm volatile("cp.async.wait_group 0;" ::: "memory");
}

// ---------------- kernel 1: detect index dtype + zero accumulators ----------
// N_EDGES threads; N_EDGES == N_NODES*HDIM/4 so the same range covers zeroing.
// g_orhigh is zeroed by a cudaMemsetAsync issued before this kernel.
__global__ void k_detect(const unsigned* __restrict__ raw) {
    int i = blockIdx.x * blockDim.x + threadIdx.x;
    float4 z = make_float4(0.f, 0.f, 0.f, 0.f);
    if (i < N_NODES * HDIM / 4) {
        reinterpret_cast<float4*>(g_wV)[i] = z;
        reinterpret_cast<float4*>(g_rowV)[i] = z;
    }
    if (i < N_NODES * HEADS / 4) reinterpret_cast<float4*>(g_den)[i] = z;
    unsigned hi = (i < N_EDGES) ? raw[2 * i + 1] : 0u;
    hi = __reduce_or_sync(0xffffffffu, hi);
    if ((threadIdx.x & 31) == 0 && hi) atomicOr(&g_orhigh, hi);
}

// ---------------- kernel 2: node projections Q,K,V (parallel over y) --------
__global__ void k_nodeproj(const float* __restrict__ x,
                           const float* __restrict__ Wq, const float* __restrict__ bq,
                           const float* __restrict__ Wk, const float* __restrict__ bk,
                           const float* __restrict__ Wv, const float* __restrict__ bv) {
    __shared__ float sW[64 * 64];
    __shared__ float sA[8][4][64];
    const int tid = threadIdx.x, warp = tid >> 5, lane = tid & 31;
    const int n0 = (blockIdx.x * 8 + warp) * 4;

    const float* W; const float* B; float* OUT;
    if (blockIdx.y == 0)      { W = Wq; B = bq; OUT = g_Qh; }
    else if (blockIdx.y == 1) { W = Wk; B = bk; OUT = g_Kh; }
    else                      { W = Wv; B = bv; OUT = g_Vh; }

    #pragma unroll
    for (int n = 0; n < 4; n++) {
        int node = n0 + n; if (node >= N_NODES) node = N_NODES - 1;
        sA[warp][n][lane]      = x[(size_t)node * 64 + lane];
        sA[warp][n][lane + 32] = x[(size_t)node * 64 + lane + 32];
    }
    for (int i = tid; i < 4096; i += 256) sW[i] = W[i];
    __syncthreads();

    float b0 = B[lane], b1 = B[lane + 32];
    float a0c0 = b0, a0c1 = b1, a1c0 = b0, a1c1 = b1;
    float a2c0 = b0, a2c1 = b1, a3c0 = b0, a3c1 = b1;
    #pragma unroll 16
    for (int k = 0; k < 64; k++) {
        float w0 = sW[k * 64 + lane], w1 = sW[k * 64 + lane + 32];
        float a0 = sA[warp][0][k], a1 = sA[warp][1][k];
        float a2 = sA[warp][2][k], a3 = sA[warp][3][k];
        a0c0 = fmaf(a0, w0, a0c0); a0c1 = fmaf(a0, w1, a0c1);
        a1c0 = fmaf(a1, w0, a1c0); a1c1 = fmaf(a1, w1, a1c1);
        a2c0 = fmaf(a2, w0, a2c0); a2c1 = fmaf(a2, w1, a2c1);
        a3c0 = fmaf(a3, w0, a3c0); a3c1 = fmaf(a3, w1, a3c1);
    }
    if (n0 + 0 < N_NODES) { OUT[(size_t)(n0+0)*64+lane]=a0c0; OUT[(size_t)(n0+0)*64+lane+32]=a0c1; }
    if (n0 + 1 < N_NODES) { OUT[(size_t)(n0+1)*64+lane]=a1c0; OUT[(size_t)(n0+1)*64+lane+32]=a1c1; }
    if (n0 + 2 < N_NODES) { OUT[(size_t)(n0+2)*64+lane]=a2c0; OUT[(size_t)(n0+2)*64+lane+32]=a2c1; }
    if (n0 + 3 < N_NODES) { OUT[(size_t)(n0+3)*64+lane]=a3c0; OUT[(size_t)(n0+3)*64+lane+32]=a3c1; }
}

// ---------------- kernel 3: fused edge kernel ----------------
// ne=4, occ 3. Per tile: attrs (evict-first L2) + K/Q/V prefetched via 16B
// cp.async; KQV group waited only AFTER the GEMM. Phase C all-smem operands.
__global__ void __launch_bounds__(256, 3)
k_edge(const float* __restrict__ edge_attr,
       const void* __restrict__ ei_raw,
       const float* __restrict__ We, const float* __restrict__ be,
       const float* __restrict__ Aw,
       float* __restrict__ wE_out) {
    extern __shared__ float smem[];
    float* sWT  = smem;                                   // [128][W_STRIDE]
    float* sEA  = smem + SMEM_WT_FLOATS;                  // [32][EA_STRIDE]
    float* sKQV = smem + SMEM_WT_FLOATS + SMEM_EA_FLOATS; // [32][KQV_STRIDE]
    __shared__ float sP[8][4][8];                         // exp(s) [warp][edge][head]

    const int tid = threadIdx.x, warp = tid >> 5, lane = tid & 31;
    const int e_loc0 = warp * 4;

    for (int i = tid; i < 128 * 64; i += 256) {
        int c = i & 127, k = i >> 7;
        sWT[c * W_STRIDE + k] = We[k * 128 + c];
    }
    __syncthreads();

    const int d0 = lane & 7, h0 = lane >> 3;
    const int cw = (h0 << 4) + d0;
    const float aw0 = Aw[d0 * 8 + h0];
    const float aw1 = Aw[d0 * 8 + h0 + 4];

    const unsigned long long bini0 = pack2(be[cw],      0.f);
    const unsigned long long bini1 = pack2(be[cw + 8],  0.f);
    const unsigned long long bini2 = pack2(be[cw + 64], 0.f);
    const unsigned long long bini3 = pack2(be[cw + 72], 0.f);

    const float* wrow0 = &sWT[(cw)      * W_STRIDE];
    const float* wrow1 = &sWT[(cw + 8)  * W_STRIDE];
    const float* wrow2 = &sWT[(cw + 64) * W_STRIDE];
    const float* wrow3 = &sWT[(cw + 72) * W_STRIDE];

    const bool idx64 = (g_orhigh == 0u);
    const long long* p64 = (const long long*)ei_raw;
    const int*       p32 = (const int*)ei_raw;

    const int l16 = lane & 15, lh = lane >> 4;

    const uint32_t ea_smem = (uint32_t)__cvta_generic_to_shared(
        &sEA[e_loc0 * EA_STRIDE]);
    const uint32_t kqv_smem = (uint32_t)__cvta_generic_to_shared(
        &sKQV[e_loc0 * KQV_STRIDE]);

    for (int tile = blockIdx.x; tile < TILES; tile += gridDim.x) {
        const int e0 = tile * 32 + e_loc0;

        int srcs[4], dsts[4];
        if (idx64) {
            #pragma unroll
            for (int n = 0; n < 4; n++) {
                srcs[n] = (int)__ldg(&p64[e0 + n]);
                dsts[n] = (int)__ldg(&p64[N_EDGES + e0 + n]);
            }
        } else {
            #pragma unroll
            for (int n = 0; n < 4; n++) {
                srcs[n] = __ldg(&p32[e0 + n]);
                dsts[n] = __ldg(&p32[N_EDGES + e0 + n]);
            }
        }

        // group 0: edge attrs (streaming, evict-first L2)
        #pragma unroll
        for (int m = 0; m < 2; m++) {
            const float* ga = &edge_attr[(size_t)(e0 + 2 * m + lh) * 64 + l16 * 4];
            cp_async16_stream(ea_smem + (uint32_t)((2 * m + lh) * EA_STRIDE + l16 * 4) * 4u, ga);
        }
        cp_commit();

        // group 1: K/Q (4x cp16) + V (2x cp16), covered by GEMM
        #pragma unroll
        for (int n = 0; n < 4; n++) {
            const float* s = (lh == 0)
                ? &g_Kh[(size_t)srcs[n] * 64 + l16 * 4]
                : &g_Qh[(size_t)dsts[n] * 64 + l16 * 4];
            cp_async16(kqv_smem + (uint32_t)(n * KQV_STRIDE + lh * 64 + l16 * 4) * 4u, s);
        }
        #pragma unroll
        for (int m = 0; m < 2; m++) {
            int sv = (lh == 0) ? srcs[2 * m] : srcs[2 * m + 1];
            const float* s = &g_Vh[(size_t)sv * 64 + l16 * 4];
            cp_async16(kqv_smem + (uint32_t)((2 * m + lh) * KQV_STRIDE + 128 + l16 * 4) * 4u, s);
        }
        cp_commit();

        cp_wait1();
        __syncwarp();

        // GEMM: 4 edges x 4 cols, FFMA2 (even-k, odd-k) lanes
        unsigned long long acc[4][4];
        #pragma unroll
        for (int e = 0; e < 4; e++) {
            acc[e][0] = bini0; acc[e][1] = bini1;
            acc[e][2] = bini2; acc[e][3] = bini3;
        }

        #pragma unroll 4
        for (int k4 = 0; k4 < 64; k4 += 4) {
            ulonglong2 ww0 = *reinterpret_cast<const ulonglong2*>(wrow0 + k4);
            ulonglong2 ww1 = *reinterpret_cast<const ulonglong2*>(wrow1 + k4);
            ulonglong2 ww2 = *reinterpret_cast<const ulonglong2*>(wrow2 + k4);
            ulonglong2 ww3 = *reinterpret_cast<const ulonglong2*>(wrow3 + k4);
            #pragma unroll
            for (int e = 0; e < 4; e++) {
                ulonglong2 aa = *reinterpret_cast<const ulonglong2*>(
                    &sEA[(e_loc0 + e) * EA_STRIDE + k4]);
                ffma2(acc[e][0], aa.x, ww0.x); ffma2(acc[e][0], aa.y, ww0.y);
                ffma2(acc[e][1], aa.x, ww1.x); ffma2(acc[e][1], aa.y, ww1.y);
                ffma2(acc[e][2], aa.x, ww2.x); ffma2(acc[e][2], aa.y, ww2.y);
                ffma2(acc[e][3], aa.x, ww3.x); ffma2(acc[e][3], aa.y, ww3.y);
            }
        }

        cp_wait0();
        __syncwarp();

        // phase B: scores (stcs + smem stash), per-head exp, den red
        #pragma unroll
        for (int n = 0; n < 4; n++) {
            int e = e0 + n;
            int dst = dsts[n];
            const float* kqv = &sKQV[(e_loc0 + n) * KQV_STRIDE];
            float ew0 = sum2(acc[n][0]);
            float eb0 = sum2(acc[n][1]);
            float ew1 = sum2(acc[n][2]);
            float eb1 = sum2(acc[n][3]);

            float kq0 = kqv[lane]      + kqv[lane + 64];
            float kq1 = kqv[lane + 32] + kqv[lane + 96];
            float sc0 = signed_sqrt(kq0 * ew0) + eb0;
            float sc1 = signed_sqrt(kq1 * ew1) + eb1;

            __stcs(&wE_out[(size_t)e * 64 + lane],      sc0);
            __stcs(&wE_out[(size_t)e * 64 + lane + 32], sc1);
            float* srow = &sEA[(e_loc0 + n) * EA_STRIDE];
            srow[lane]      = sc0;
            srow[lane + 32] = sc1;

            float p0 = sc0 * aw0;
            float p1 = sc1 * aw1;
            #pragma unroll
            for (int off = 4; off > 0; off >>= 1) {
                p0 += __shfl_xor_sync(0xffffffffu, p0, off);
                p1 += __shfl_xor_sync(0xffffffffu, p1, off);
            }
            p0 = __expf(fminf(fmaxf(p0, -CLAMP_V), CLAMP_V));
            p1 = __expf(fminf(fmaxf(p1, -CLAMP_V), CLAMP_V));
            if (d0 == 0) {
                sP[warp][n][h0]     = p0;
                sP[warp][n][h0 + 4] = p1;
                redAdd1(&g_den[(size_t)dst * 8 + h0],     p0);
                redAdd1(&g_den[(size_t)dst * 8 + h0 + 4], p1);
            }
        }
        __syncwarp();

        // phase C: numerator scatter (all operands in smem)
        const int q  = lane & 15;
        const int j0 = q * 4;
        const int hq = q >> 1;
        #pragma unroll
        for (int n = 0; n < 4; n++) {
            float p = sP[warp][n][hq];
            int dst = dsts[n];
            if (lane < 16) {
                float4 v = *reinterpret_cast<const float4*>(
                    &sKQV[(e_loc0 + n) * KQV_STRIDE + 128 + j0]);
                redAddV4(&g_wV[(size_t)dst * 64 + j0], v.x * p, v.y * p, v.z * p, v.w * p);
            } else {
                float4 et = *reinterpret_cast<const float4*>(
                    &sEA[(e_loc0 + n) * EA_STRIDE + j0]);
                redAddV4(&g_rowV[(size_t)dst * 64 + j0], et.x * p, et.y * p, et.z * p, et.w * p);
            }
        }
        __syncwarp();
    }
}

// ---------------- kernel 4: finalize wV = (wV_raw + rowV_raw @ VeRow) / den ----
__global__ void k_final(const float* __restrict__ VeRow, float* __restrict__ wV_out) {
    int i = blockIdx.x * blockDim.x + threadIdx.x;
    if (i >= N_NODES * HDIM) return;
    int n = i >> 6, j = i & 63;
    int h = j >> 3, c = j & 7;
    float inv = 1.0f / (g_den[(size_t)n * 8 + h] + 1e-16f);
    float acc = g_wV[i];
    const float* rv = &g_rowV[(size_t)n * 64 + h * 8];
    #pragma unroll
    for (int d = 0; d < 8; d++)
        acc = fmaf(rv[d], __ldg(&VeRow[d * 64 + h * 8 + c]), acc);
    wV_out[i] = acc * inv;
}

// ---------------- launch ----------------
extern "C" void kernel_launch(void* const* d_in, const int* in_sizes, int n_in,
                              void* d_out, int out_size) {
    const float* x         = (const float*)d_in[0];
    const float* edge_attr = (const float*)d_in[1];
    const void*  ei_raw    = d_in[2];
    const float* Wq = (const float*)d_in[3];
    const float* bq = (const float*)d_in[4];
    const float* Wk = (const float*)d_in[5];
    const float* bk = (const float*)d_in[6];
    const float* We = (const float*)d_in[7];
    const float* be = (const float*)d_in[8];
    const float* Wv = (const float*)d_in[9];
    const float* bv = (const float*)d_in[10];
    const float* Aw = (const float*)d_in[11];
    const float* VeRow = (const float*)d_in[12];

    float* out    = (float*)d_out;
    float* wV_out = out;
    float* wE_out = out + (size_t)N_NODES * HDIM;

    cudaFuncSetAttribute(k_edge, cudaFuncAttributeMaxDynamicSharedMemorySize,
                         SMEM_EDGE_BYTES);

    void* flag_ptr = nullptr;
    cudaGetSymbolAddress(&flag_ptr, g_orhigh);
    cudaMemsetAsync(flag_ptr, 0, sizeof(unsigned));

    k_detect<<<(N_EDGES + 255) / 256, 256>>>((const unsigned*)ei_raw);
    dim3 npgrid((N_NODES + 31) / 32, 3);
    k_nodeproj<<<npgrid, 256>>>(x, Wq, bq, Wk, bk, Wv, bv);
    k_edge<<<EDGE_GRID, 256, SMEM_EDGE_BYTES>>>(edge_attr, ei_raw, We, be, Aw, wE_out);
    k_final<<<(N_NODES * HDIM + 255) / 256, 256>>>(VeRow, wV_out);
}

// round 14
// speedup vs baseline: 1.1728x; 1.0341x over previous
#include <cuda_runtime.h>
#include <math.h>
#include <stdint.h>

#define N_NODES 50000
#define N_EDGES 800000
#define HEADS   8
#define ODIM    8
#define HDIM    64
#define CLAMP_V 5.0f
#define EPS_V   1e-8f
#define SQRT_EPS 9.9999997e-05f     // fp32 sqrt(1e-8)
#define EDGE_GRID 444               // 148 SMs * 3 persistent blocks
#define NCHUNK  (N_EDGES / 16)      // 50000 16-edge work units

#define W_STRIDE   68               // sWT row stride in floats (272B, 16B-aligned)
#define EA_STRIDE  68               // sEA row stride (attrs, then scores)
#define KQV_STRIDE 192              // per-edge: K(64) Q(64) V(64)
#define SMEM_WT_FLOATS  (128 * W_STRIDE)     // 8704
#define SMEM_EA_FLOATS  (32 * EA_STRIDE)     // 2176
#define SMEM_KQV_FLOATS (32 * KQV_STRIDE)    // 6144
#define SMEM_EDGE_BYTES ((SMEM_WT_FLOATS + SMEM_EA_FLOATS + SMEM_KQV_FLOATS) * 4) // 68096

// ---------------- device scratch ----------------
__device__ __align__(16) float g_Qh[N_NODES * HDIM];
__device__ __align__(16) float g_Kh[N_NODES * HDIM];
__device__ __align__(16) float g_Vh[N_NODES * HDIM];
__device__ __align__(16) float g_den[N_NODES * HEADS];
__device__ __align__(16) float g_wV  [N_NODES * HDIM];
__device__ __align__(16) float g_rowV[N_NODES * HDIM];
__device__ unsigned g_orhigh;
__device__ unsigned g_wctr;

// ---------------- helpers ----------------
__device__ __forceinline__ void redAddV4(float* p, float a, float b, float c, float d) {
    asm volatile("red.global.add.v4.f32 [%0], {%1,%2,%3,%4};"
                 :: "l"(p), "f"(a), "f"(b), "f"(c), "f"(d) : "memory");
}
__device__ __forceinline__ void redAdd1(float* p, float v) {
    asm volatile("red.global.add.f32 [%0], %1;" :: "l"(p), "f"(v) : "memory");
}
__device__ __forceinline__ void ffma2(unsigned long long& acc,
                                      unsigned long long a, unsigned long long b) {
    asm("fma.rn.f32x2 %0, %1, %2, %0;" : "+l"(acc) : "l"(a), "l"(b));
}
__device__ __forceinline__ unsigned long long pack2(float lo, float hi) {
    unsigned long long r;
    asm("mov.b64 %0, {%1,%2};" : "=l"(r) : "f"(lo), "f"(hi));
    return r;
}
__device__ __forceinline__ float sum2(unsigned long long v) {
    float2 r;
    asm("mov.b64 {%0,%1}, %2;" : "=f"(r.x), "=f"(r.y) : "l"(v));
    return r.x + r.y;
}
__device__ __forceinline__ float fsqrt_ap(float x) {
    float r; asm("sqrt.approx.f32 %0, %1;" : "=f"(r) : "f"(x)); return r;
}
// sqrt(relu(x)+eps) - sqrt(relu(-x)+eps) == copysign(sqrt(|x|+eps)-sqrt(eps), x)
__device__ __forceinline__ float signed_sqrt(float x) {
    float t = fsqrt_ap(fabsf(x) + EPS_V) - SQRT_EPS;
    return copysignf(t, x);
}
__device__ __forceinline__ void cp_async16(uint32_t smem_addr, const void* gptr) {
    asm volatile("cp.async.cg.shared.global [%0], [%1], 16;"
                 :: "r"(smem_addr), "l"(gptr));
}
// evict-first L2 policy for the big streaming edge_attr reads
__device__ __forceinline__ void cp_async16_stream(uint32_t smem_addr, const void* gptr) {
    asm volatile(
        "{\n\t"
        ".reg .b64 pol;\n\t"
        "createpolicy.fractional.L2::evict_first.b64 pol, 1.0;\n\t"
        "cp.async.cg.shared.global.L2::cache_hint [%0], [%1], 16, pol;\n\t"
        "}"
        :: "r"(smem_addr), "l"(gptr));
}
__device__ __forceinline__ void cp_commit() {
    asm volatile("cp.async.commit_group;" ::: "memory");
}
__device__ __forceinline__ void cp_wait1() {
    asm volatile("cp.async.wait_group 1;" ::: "memory");
}
__device__ __forceinline__ void cp_wait0() {
    asm volatile("cp.async.wait_group 0;" ::: "memory");
}

// ---------------- kernel 1: detect index dtype + zero accumulators ----------
// g_orhigh / g_wctr are zeroed via cudaMemsetAsync before this kernel.
__global__ void k_detect(const unsigned* __restrict__ raw) {
    int i = blockIdx.x * blockDim.x + threadIdx.x;
    float4 z = make_float4(0.f, 0.f, 0.f, 0.f);
    if (i < N_NODES * HDIM / 4) {
        reinterpret_cast<float4*>(g_wV)[i] = z;
        reinterpret_cast<float4*>(g_rowV)[i] = z;
    }
    if (i < N_NODES * HEADS / 4) reinterpret_cast<float4*>(g_den)[i] = z;
    unsigned hi = (i < N_EDGES) ? raw[2 * i + 1] : 0u;
    hi = __reduce_or_sync(0xffffffffu, hi);
    if ((threadIdx.x & 31) == 0 && hi) atomicOr(&g_orhigh, hi);
}

// ---------------- kernel 2: node projections Q,K,V (parallel over y) --------
__global__ void k_nodeproj(const float* __restrict__ x,
                           const float* __restrict__ Wq, const float* __restrict__ bq,
                           const float* __restrict__ Wk, const float* __restrict__ bk,
                           const float* __restrict__ Wv, const float* __restrict__ bv) {
    __shared__ float sW[64 * 64];
    __shared__ float sA[8][4][64];
    const int tid = threadIdx.x, warp = tid >> 5, lane = tid & 31;
    const int n0 = (blockIdx.x * 8 + warp) * 4;

    const float* W; const float* B; float* OUT;
    if (blockIdx.y == 0)      { W = Wq; B = bq; OUT = g_Qh; }
    else if (blockIdx.y == 1) { W = Wk; B = bk; OUT = g_Kh; }
    else                      { W = Wv; B = bv; OUT = g_Vh; }

    #pragma unroll
    for (int n = 0; n < 4; n++) {
        int node = n0 + n; if (node >= N_NODES) node = N_NODES - 1;
        sA[warp][n][lane]      = x[(size_t)node * 64 + lane];
        sA[warp][n][lane + 32] = x[(size_t)node * 64 + lane + 32];
    }
    for (int i = tid; i < 4096; i += 256) sW[i] = W[i];
    __syncthreads();

    float b0 = B[lane], b1 = B[lane + 32];
    float a0c0 = b0, a0c1 = b1, a1c0 = b0, a1c1 = b1;
    float a2c0 = b0, a2c1 = b1, a3c0 = b0, a3c1 = b1;
    #pragma unroll 16
    for (int k = 0; k < 64; k++) {
        float w0 = sW[k * 64 + lane], w1 = sW[k * 64 + lane + 32];
        float a0 = sA[warp][0][k], a1 = sA[warp][1][k];
        float a2 = sA[warp][2][k], a3 = sA[warp][3][k];
        a0c0 = fmaf(a0, w0, a0c0); a0c1 = fmaf(a0, w1, a0c1);
        a1c0 = fmaf(a1, w0, a1c0); a1c1 = fmaf(a1, w1, a1c1);
        a2c0 = fmaf(a2, w0, a2c0); a2c1 = fmaf(a2, w1, a2c1);
        a3c0 = fmaf(a3, w0, a3c0); a3c1 = fmaf(a3, w1, a3c1);
    }
    if (n0 + 0 < N_NODES) { OUT[(size_t)(n0+0)*64+lane]=a0c0; OUT[(size_t)(n0+0)*64+lane+32]=a0c1; }
    if (n0 + 1 < N_NODES) { OUT[(size_t)(n0+1)*64+lane]=a1c0; OUT[(size_t)(n0+1)*64+lane+32]=a1c1; }
    if (n0 + 2 < N_NODES) { OUT[(size_t)(n0+2)*64+lane]=a2c0; OUT[(size_t)(n0+2)*64+lane+32]=a2c1; }
    if (n0 + 3 < N_NODES) { OUT[(size_t)(n0+3)*64+lane]=a3c0; OUT[(size_t)(n0+3)*64+lane+32]=a3c1; }
}

// ---------------- kernel 3: fused edge kernel (dynamic warp scheduler) ------
// Warps independently grab 16-edge chunks via atomicAdd(g_wctr); the next
// chunk's atomic is issued at chunk start and shfl'd only at chunk end, so
// its latency hides under ~6000 cycles of work. Body per 4-edge group is
// identical to R13. smem regions remain per-warp (e_loc0).
__global__ void __launch_bounds__(256, 3)
k_edge(const float* __restrict__ edge_attr,
       const void* __restrict__ ei_raw,
       const float* __restrict__ We, const float* __restrict__ be,
       const float* __restrict__ Aw,
       float* __restrict__ wE_out) {
    extern __shared__ float smem[];
    float* sWT  = smem;                                   // [128][W_STRIDE]
    float* sEA  = smem + SMEM_WT_FLOATS;                  // [32][EA_STRIDE]
    float* sKQV = smem + SMEM_WT_FLOATS + SMEM_EA_FLOATS; // [32][KQV_STRIDE]
    __shared__ float sP[8][4][8];                         // exp(s) [warp][edge][head]

    const int tid = threadIdx.x, warp = tid >> 5, lane = tid & 31;
    const int e_loc0 = warp * 4;

    for (int i = tid; i < 128 * 64; i += 256) {
        int c = i & 127, k = i >> 7;
        sWT[c * W_STRIDE + k] = We[k * 128 + c];
    }
    __syncthreads();

    const int d0 = lane & 7, h0 = lane >> 3;
    const int cw = (h0 << 4) + d0;
    const float aw0 = Aw[d0 * 8 + h0];
    const float aw1 = Aw[d0 * 8 + h0 + 4];

    const unsigned long long bini0 = pack2(be[cw],      0.f);
    const unsigned long long bini1 = pack2(be[cw + 8],  0.f);
    const unsigned long long bini2 = pack2(be[cw + 64], 0.f);
    const unsigned long long bini3 = pack2(be[cw + 72], 0.f);

    const float* wrow0 = &sWT[(cw)      * W_STRIDE];
    const float* wrow1 = &sWT[(cw + 8)  * W_STRIDE];
    const float* wrow2 = &sWT[(cw + 64) * W_STRIDE];
    const float* wrow3 = &sWT[(cw + 72) * W_STRIDE];

    const bool idx64 = (g_orhigh == 0u);
    const long long* p64 = (const long long*)ei_raw;
    const int*       p32 = (const int*)ei_raw;

    const int l16 = lane & 15, lh = lane >> 4;

    const uint32_t ea_smem = (uint32_t)__cvta_generic_to_shared(
        &sEA[e_loc0 * EA_STRIDE]);
    const uint32_t kqv_smem = (uint32_t)__cvta_generic_to_shared(
        &sKQV[e_loc0 * KQV_STRIDE]);

    // ---- dynamic scheduler: grab first chunk ----
    unsigned chunk = 0;
    if (lane == 0) chunk = atomicAdd(&g_wctr, 1u);
    chunk = __shfl_sync(0xffffffffu, chunk, 0);

    while (chunk < NCHUNK) {
        // issue next-chunk atomic now; consume its value at chunk end
        unsigned next_raw = 0;
        if (lane == 0) next_raw = atomicAdd(&g_wctr, 1u);

        #pragma unroll 1
        for (int g = 0; g < 4; g++) {
            const int e0 = (int)chunk * 16 + g * 4;

            int srcs[4], dsts[4];
            if (idx64) {
                #pragma unroll
                for (int n = 0; n < 4; n++) {
                    srcs[n] = (int)__ldg(&p64[e0 + n]);
                    dsts[n] = (int)__ldg(&p64[N_EDGES + e0 + n]);
                }
            } else {
                #pragma unroll
                for (int n = 0; n < 4; n++) {
                    srcs[n] = __ldg(&p32[e0 + n]);
                    dsts[n] = __ldg(&p32[N_EDGES + e0 + n]);
                }
            }

            // group 0: edge attrs (streaming, evict-first L2)
            #pragma unroll
            for (int m = 0; m < 2; m++) {
                const float* ga = &edge_attr[(size_t)(e0 + 2 * m + lh) * 64 + l16 * 4];
                cp_async16_stream(ea_smem + (uint32_t)((2 * m + lh) * EA_STRIDE + l16 * 4) * 4u, ga);
            }
            cp_commit();

            // group 1: K/Q (4x cp16) + V (2x cp16), covered by GEMM
            #pragma unroll
            for (int n = 0; n < 4; n++) {
                const float* s = (lh == 0)
                    ? &g_Kh[(size_t)srcs[n] * 64 + l16 * 4]
                    : &g_Qh[(size_t)dsts[n] * 64 + l16 * 4];
                cp_async16(kqv_smem + (uint32_t)(n * KQV_STRIDE + lh * 64 + l16 * 4) * 4u, s);
            }
            #pragma unroll
            for (int m = 0; m < 2; m++) {
                int sv = (lh == 0) ? srcs[2 * m] : srcs[2 * m + 1];
                const float* s = &g_Vh[(size_t)sv * 64 + l16 * 4];
                cp_async16(kqv_smem + (uint32_t)((2 * m + lh) * KQV_STRIDE + 128 + l16 * 4) * 4u, s);
            }
            cp_commit();

            cp_wait1();
            __syncwarp();

            // GEMM: 4 edges x 4 cols, FFMA2 (even-k, odd-k) lanes
            unsigned long long acc[4][4];
            #pragma unroll
            for (int e = 0; e < 4; e++) {
                acc[e][0] = bini0; acc[e][1] = bini1;
                acc[e][2] = bini2; acc[e][3] = bini3;
            }

            #pragma unroll 4
            for (int k4 = 0; k4 < 64; k4 += 4) {
                ulonglong2 ww0 = *reinterpret_cast<const ulonglong2*>(wrow0 + k4);
                ulonglong2 ww1 = *reinterpret_cast<const ulonglong2*>(wrow1 + k4);
                ulonglong2 ww2 = *reinterpret_cast<const ulonglong2*>(wrow2 + k4);
                ulonglong2 ww3 = *reinterpret_cast<const ulonglong2*>(wrow3 + k4);
                #pragma unroll
                for (int e = 0; e < 4; e++) {
                    ulonglong2 aa = *reinterpret_cast<const ulonglong2*>(
                        &sEA[(e_loc0 + e) * EA_STRIDE + k4]);
                    ffma2(acc[e][0], aa.x, ww0.x); ffma2(acc[e][0], aa.y, ww0.y);
                    ffma2(acc[e][1], aa.x, ww1.x); ffma2(acc[e][1], aa.y, ww1.y);
                    ffma2(acc[e][2], aa.x, ww2.x); ffma2(acc[e][2], aa.y, ww2.y);
                    ffma2(acc[e][3], aa.x, ww3.x); ffma2(acc[e][3], aa.y, ww3.y);
                }
            }

            cp_wait0();
            __syncwarp();

            // phase B: scores (stcs + smem stash), per-head exp, den red
            #pragma unroll
            for (int n = 0; n < 4; n++) {
                int e = e0 + n;
                int dst = dsts[n];
                const float* kqv = &sKQV[(e_loc0 + n) * KQV_STRIDE];
                float ew0 = sum2(acc[n][0]);
                float eb0 = sum2(acc[n][1]);
                float ew1 = sum2(acc[n][2]);
                float eb1 = sum2(acc[n][3]);

                float kq0 = kqv[lane]      + kqv[lane + 64];
                float kq1 = kqv[lane + 32] + kqv[lane + 96];
                float sc0 = signed_sqrt(kq0 * ew0) + eb0;
                float sc1 = signed_sqrt(kq1 * ew1) + eb1;

                __stcs(&wE_out[(size_t)e * 64 + lane],      sc0);
                __stcs(&wE_out[(size_t)e * 64 + lane + 32], sc1);
                float* srow = &sEA[(e_loc0 + n) * EA_STRIDE];
                srow[lane]      = sc0;
                srow[lane + 32] = sc1;

                float p0 = sc0 * aw0;
                float p1 = sc1 * aw1;
                #pragma unroll
                for (int off = 4; off > 0; off >>= 1) {
                    p0 += __shfl_xor_sync(0xffffffffu, p0, off);
                    p1 += __shfl_xor_sync(0xffffffffu, p1, off);
                }
                p0 = __expf(fminf(fmaxf(p0, -CLAMP_V), CLAMP_V));
                p1 = __expf(fminf(fmaxf(p1, -CLAMP_V), CLAMP_V));
                if (d0 == 0) {
                    sP[warp][n][h0]     = p0;
                    sP[warp][n][h0 + 4] = p1;
                    redAdd1(&g_den[(size_t)dst * 8 + h0],     p0);
                    redAdd1(&g_den[(size_t)dst * 8 + h0 + 4], p1);
                }
            }
            __syncwarp();

            // phase C: numerator scatter (all operands in smem)
            const int q  = lane & 15;
            const int j0 = q * 4;
            const int hq = q >> 1;
            #pragma unroll
            for (int n = 0; n < 4; n++) {
                float p = sP[warp][n][hq];
                int dst = dsts[n];
                if (lane < 16) {
                    float4 v = *reinterpret_cast<const float4*>(
                        &sKQV[(e_loc0 + n) * KQV_STRIDE + 128 + j0]);
                    redAddV4(&g_wV[(size_t)dst * 64 + j0], v.x * p, v.y * p, v.z * p, v.w * p);
                } else {
                    float4 et = *reinterpret_cast<const float4*>(
                        &sEA[(e_loc0 + n) * EA_STRIDE + j0]);
                    redAddV4(&g_rowV[(size_t)dst * 64 + j0], et.x * p, et.y * p, et.z * p, et.w * p);
                }
            }
            __syncwarp();
        }

        chunk = __shfl_sync(0xffffffffu, next_raw, 0);   // atomic long since done
    }
}

// ---------------- kernel 4: finalize (8 outputs per thread) ----------------
// wV = (wV_raw + rowV_raw @ VeRow) / den, one (node, head) row per thread.
__global__ void k_final(const float* __restrict__ VeRow, float* __restrict__ wV_out) {
    __shared__ float sV[512];                 // VeRow[d][h*8+c] : 64x8x... 4KB? no: 8*64=512
    for (int i = threadIdx.x; i < 512; i += 256) sV[i] = VeRow[i];
    __syncthreads();

    int i = blockIdx.x * blockDim.x + threadIdx.x;
    if (i >= N_NODES * HEADS) return;
    int n = i >> 3, h = i & 7;
    float inv = 1.0f / (g_den[i] + 1e-16f);

    const float* rvp = &g_rowV[(size_t)n * 64 + h * 8];
    float4 rv0 = *reinterpret_cast<const float4*>(rvp);
    float4 rv1 = *reinterpret_cast<const float4*>(rvp + 4);
    float rv[8] = { rv0.x, rv0.y, rv0.z, rv0.w, rv1.x, rv1.y, rv1.z, rv1.w };

    const float* wvp = &g_wV[(size_t)n * 64 + h * 8];
    float4 wv0 = *reinterpret_cast<const float4*>(wvp);
    float4 wv1 = *reinterpret_cast<const float4*>(wvp + 4);
    float acc[8] = { wv0.x, wv0.y, wv0.z, wv0.w, wv1.x, wv1.y, wv1.z, wv1.w };

    #pragma unroll
    for (int d = 0; d < 8; d++) {
        float r = rv[d];
        const float* vc = &sV[d * 64 + h * 8];
        #pragma unroll
        for (int c = 0; c < 8; c++)
            acc[c] = fmaf(r, vc[c], acc[c]);
    }
    float* op = &wV_out[(size_t)n * 64 + h * 8];
    *reinterpret_cast<float4*>(op)     = make_float4(acc[0]*inv, acc[1]*inv, acc[2]*inv, acc[3]*inv);
    *reinterpret_cast<float4*>(op + 4) = make_float4(acc[4]*inv, acc[5]*inv, acc[6]*inv, acc[7]*inv);
}

// ---------------- launch ----------------
extern "C" void kernel_launch(void* const* d_in, const int* in_sizes, int n_in,
                              void* d_out, int out_size) {
    const float* x         = (const float*)d_in[0];
    const float* edge_attr = (const float*)d_in[1];
    const void*  ei_raw    = d_in[2];
    const float* Wq = (const float*)d_in[3];
    const float* bq = (const float*)d_in[4];
    const float* Wk = (const float*)d_in[5];
    const float* bk = (const float*)d_in[6];
    const float* We = (const float*)d_in[7];
    const float* be = (const float*)d_in[8];
    const float* Wv = (const float*)d_in[9];
    const float* bv = (const float*)d_in[10];
    const float* Aw = (const float*)d_in[11];
    const float* VeRow = (const float*)d_in[12];

    float* out    = (float*)d_out;
    float* wV_out = out;
    float* wE_out = out + (size_t)N_NODES * HDIM;

    cudaFuncSetAttribute(k_edge, cudaFuncAttributeMaxDynamicSharedMemorySize,
                         SMEM_EDGE_BYTES);

    void* flag_ptr = nullptr;
    cudaGetSymbolAddress(&flag_ptr, g_orhigh);
    cudaMemsetAsync(flag_ptr, 0, sizeof(unsigned));
    void* ctr_ptr = nullptr;
    cudaGetSymbolAddress(&ctr_ptr, g_wctr);
    cudaMemsetAsync(ctr_ptr, 0, sizeof(unsigned));

    k_detect<<<(N_EDGES + 255) / 256, 256>>>((const unsigned*)ei_raw);
    dim3 npgrid((N_NODES + 31) / 32, 3);
    k_nodeproj<<<npgrid, 256>>>(x, Wq, bq, Wk, bk, Wv, bv);
    k_edge<<<EDGE_GRID, 256, SMEM_EDGE_BYTES>>>(edge_attr, ei_raw, We, be, Aw, wE_out);
    k_final<<<(N_NODES * HEADS + 255) / 256, 256>>>(VeRow, wV_out);
}

// round 15
// speedup vs baseline: 1.2175x; 1.0381x over previous
#include <cuda_runtime.h>
#include <math.h>
#include <stdint.h>

#define N_NODES 50000
#define N_EDGES 800000
#define HEADS   8
#define ODIM    8
#define HDIM    64
#define CLAMP_V 5.0f
#define EPS_V   1e-8f
#define SQRT_EPS 9.9999997e-05f     // fp32 sqrt(1e-8)
#define EDGE_GRID 444               // 148 SMs * 3 persistent blocks
#define NCHUNK  (N_EDGES / 16)      // 50000 16-edge work units

#define W_STRIDE   68               // sWT row stride in floats (272B, 16B-aligned)
#define EA_STRIDE  68               // sEA row stride (attrs, then scores)
#define KQV_STRIDE 192              // per-edge: K(64) Q(64) V(64)
#define SMEM_WT_FLOATS  (128 * W_STRIDE)     // 8704
#define SMEM_EA_FLOATS  (32 * EA_STRIDE)     // 2176
#define SMEM_KQV_FLOATS (32 * KQV_STRIDE)    // 6144
#define SMEM_EDGE_BYTES ((SMEM_WT_FLOATS + SMEM_EA_FLOATS + SMEM_KQV_FLOATS) * 4) // 68096

// ---------------- device scratch ----------------
__device__ __align__(16) float g_Qh[N_NODES * HDIM];
__device__ __align__(16) float g_Kh[N_NODES * HDIM];
__device__ __align__(16) float g_Vh[N_NODES * HDIM];
__device__ __align__(16) float g_den[N_NODES * HEADS];
__device__ __align__(16) float g_wV  [N_NODES * HDIM];
__device__ __align__(16) float g_rowV[N_NODES * HDIM];
__device__ __align__(8) unsigned g_flags[2];   // [0]=orhigh, [1]=work counter

// ---------------- helpers ----------------
__device__ __forceinline__ void redAddV4(float* p, float a, float b, float c, float d) {
    asm volatile("red.global.add.v4.f32 [%0], {%1,%2,%3,%4};"
                 :: "l"(p), "f"(a), "f"(b), "f"(c), "f"(d) : "memory");
}
__device__ __forceinline__ void redAdd1(float* p, float v) {
    asm volatile("red.global.add.f32 [%0], %1;" :: "l"(p), "f"(v) : "memory");
}
__device__ __forceinline__ void ffma2(unsigned long long& acc,
                                      unsigned long long a, unsigned long long b) {
    asm("fma.rn.f32x2 %0, %1, %2, %0;" : "+l"(acc) : "l"(a), "l"(b));
}
__device__ __forceinline__ unsigned long long pack2(float lo, float hi) {
    unsigned long long r;
    asm("mov.b64 %0, {%1,%2};" : "=l"(r) : "f"(lo), "f"(hi));
    return r;
}
__device__ __forceinline__ float sum2(unsigned long long v) {
    float2 r;
    asm("mov.b64 {%0,%1}, %2;" : "=f"(r.x), "=f"(r.y) : "l"(v));
    return r.x + r.y;
}
__device__ __forceinline__ float fsqrt_ap(float x) {
    float r; asm("sqrt.approx.f32 %0, %1;" : "=f"(r) : "f"(x)); return r;
}
// sqrt(relu(x)+eps) - sqrt(relu(-x)+eps) == copysign(sqrt(|x|+eps)-sqrt(eps), x)
__device__ __forceinline__ float signed_sqrt(float x) {
    float t = fsqrt_ap(fabsf(x) + EPS_V) - SQRT_EPS;
    return copysignf(t, x);
}
__device__ __forceinline__ void cp_async16(uint32_t smem_addr, const void* gptr) {
    asm volatile("cp.async.cg.shared.global [%0], [%1], 16;"
                 :: "r"(smem_addr), "l"(gptr));
}
// evict-first L2 policy for the big streaming edge_attr reads
__device__ __forceinline__ void cp_async16_stream(uint32_t smem_addr, const void* gptr) {
    asm volatile(
        "{\n\t"
        ".reg .b64 pol;\n\t"
        "createpolicy.fractional.L2::evict_first.b64 pol, 1.0;\n\t"
        "cp.async.cg.shared.global.L2::cache_hint [%0], [%1], 16, pol;\n\t"
        "}"
        :: "r"(smem_addr), "l"(gptr));
}
__device__ __forceinline__ void cp_commit() {
    asm volatile("cp.async.commit_group;" ::: "memory");
}
__device__ __forceinline__ void cp_wait1() {
    asm volatile("cp.async.wait_group 1;" ::: "memory");
}
__device__ __forceinline__ void cp_wait0() {
    asm volatile("cp.async.wait_group 0;" ::: "memory");
}

// ---------------- kernel 1: node projections + accumulator init + dtype detect
// grid (1563, 3): y selects the projection. Flat thread id (over all 3 planes,
// 1.2M threads) covers the 800k zero-slots and 800k index-pair probes.
// The index high-word load is issued at kernel top and consumed by the warp
// reduce at kernel end, hiding its latency under the projection GEMM.
__global__ void k_nodeproj(const float* __restrict__ x,
                           const float* __restrict__ Wq, const float* __restrict__ bq,
                           const float* __restrict__ Wk, const float* __restrict__ bk,
                           const float* __restrict__ Wv, const float* __restrict__ bv,
                           const unsigned* __restrict__ raw) {
    __shared__ float sW[64 * 64];
    __shared__ float sA[8][4][64];
    const int tid = threadIdx.x, warp = tid >> 5, lane = tid & 31;
    const int n0 = (blockIdx.x * 8 + warp) * 4;

    // ---- init + detect (flat over all planes) ----
    const int flat = (blockIdx.y * gridDim.x + blockIdx.x) * 256 + tid;
    unsigned hi = (flat < N_EDGES) ? __ldg(&raw[2 * flat + 1]) : 0u;
    float4 z = make_float4(0.f, 0.f, 0.f, 0.f);
    if (flat < N_NODES * HDIM / 4) {
        reinterpret_cast<float4*>(g_wV)[flat] = z;
        reinterpret_cast<float4*>(g_rowV)[flat] = z;
    }
    if (flat < N_NODES * HEADS / 4) reinterpret_cast<float4*>(g_den)[flat] = z;

    const float* W; const float* B; float* OUT;
    if (blockIdx.y == 0)      { W = Wq; B = bq; OUT = g_Qh; }
    else if (blockIdx.y == 1) { W = Wk; B = bk; OUT = g_Kh; }
    else                      { W = Wv; B = bv; OUT = g_Vh; }

    #pragma unroll
    for (int n = 0; n < 4; n++) {
        int node = n0 + n; if (node >= N_NODES) node = N_NODES - 1;
        sA[warp][n][lane]      = x[(size_t)node * 64 + lane];
        sA[warp][n][lane + 32] = x[(size_t)node * 64 + lane + 32];
    }
    for (int i = tid; i < 4096; i += 256) sW[i] = W[i];
    __syncthreads();

    float b0 = B[lane], b1 = B[lane + 32];
    float a0c0 = b0, a0c1 = b1, a1c0 = b0, a1c1 = b1;
    float a2c0 = b0, a2c1 = b1, a3c0 = b0, a3c1 = b1;
    #pragma unroll 16
    for (int k = 0; k < 64; k++) {
        float w0 = sW[k * 64 + lane], w1 = sW[k * 64 + lane + 32];
        float a0 = sA[warp][0][k], a1 = sA[warp][1][k];
        float a2 = sA[warp][2][k], a3 = sA[warp][3][k];
        a0c0 = fmaf(a0, w0, a0c0); a0c1 = fmaf(a0, w1, a0c1);
        a1c0 = fmaf(a1, w0, a1c0); a1c1 = fmaf(a1, w1, a1c1);
        a2c0 = fmaf(a2, w0, a2c0); a2c1 = fmaf(a2, w1, a2c1);
        a3c0 = fmaf(a3, w0, a3c0); a3c1 = fmaf(a3, w1, a3c1);
    }
    if (n0 + 0 < N_NODES) { OUT[(size_t)(n0+0)*64+lane]=a0c0; OUT[(size_t)(n0+0)*64+lane+32]=a0c1; }
    if (n0 + 1 < N_NODES) { OUT[(size_t)(n0+1)*64+lane]=a1c0; OUT[(size_t)(n0+1)*64+lane+32]=a1c1; }
    if (n0 + 2 < N_NODES) { OUT[(size_t)(n0+2)*64+lane]=a2c0; OUT[(size_t)(n0+2)*64+lane+32]=a2c1; }
    if (n0 + 3 < N_NODES) { OUT[(size_t)(n0+3)*64+lane]=a3c0; OUT[(size_t)(n0+3)*64+lane+32]=a3c1; }

    // ---- finish dtype detect (value loaded at kernel top) ----
    hi = __reduce_or_sync(0xffffffffu, hi);
    if (lane == 0 && hi) atomicOr(&g_flags[0], hi);
}

// ---------------- kernel 2: fused edge kernel (dynamic warp scheduler) ------
// Warps grab 16-edge chunks via atomicAdd(g_flags[1]); next chunk's atomic is
// issued at chunk start, consumed at chunk end (latency hidden under ~6000
// cycles of work). Body identical to the 494us run.
__global__ void __launch_bounds__(256, 3)
k_edge(const float* __restrict__ edge_attr,
       const void* __restrict__ ei_raw,
       const float* __restrict__ We, const float* __restrict__ be,
       const float* __restrict__ Aw,
       float* __restrict__ wE_out) {
    extern __shared__ float smem[];
    float* sWT  = smem;                                   // [128][W_STRIDE]
    float* sEA  = smem + SMEM_WT_FLOATS;                  // [32][EA_STRIDE]
    float* sKQV = smem + SMEM_WT_FLOATS + SMEM_EA_FLOATS; // [32][KQV_STRIDE]
    __shared__ float sP[8][4][8];                         // exp(s) [warp][edge][head]

    const int tid = threadIdx.x, warp = tid >> 5, lane = tid & 31;
    const int e_loc0 = warp * 4;

    for (int i = tid; i < 128 * 64; i += 256) {
        int c = i & 127, k = i >> 7;
        sWT[c * W_STRIDE + k] = We[k * 128 + c];
    }
    __syncthreads();

    const int d0 = lane & 7, h0 = lane >> 3;
    const int cw = (h0 << 4) + d0;
    const float aw0 = Aw[d0 * 8 + h0];
    const float aw1 = Aw[d0 * 8 + h0 + 4];

    const unsigned long long bini0 = pack2(be[cw],      0.f);
    const unsigned long long bini1 = pack2(be[cw + 8],  0.f);
    const unsigned long long bini2 = pack2(be[cw + 64], 0.f);
    const unsigned long long bini3 = pack2(be[cw + 72], 0.f);

    const float* wrow0 = &sWT[(cw)      * W_STRIDE];
    const float* wrow1 = &sWT[(cw + 8)  * W_STRIDE];
    const float* wrow2 = &sWT[(cw + 64) * W_STRIDE];
    const float* wrow3 = &sWT[(cw + 72) * W_STRIDE];

    const bool idx64 = (g_flags[0] == 0u);
    const long long* p64 = (const long long*)ei_raw;
    const int*       p32 = (const int*)ei_raw;

    const int l16 = lane & 15, lh = lane >> 4;

    const uint32_t ea_smem = (uint32_t)__cvta_generic_to_shared(
        &sEA[e_loc0 * EA_STRIDE]);
    const uint32_t kqv_smem = (uint32_t)__cvta_generic_to_shared(
        &sKQV[e_loc0 * KQV_STRIDE]);

    unsigned chunk = 0;
    if (lane == 0) chunk = atomicAdd(&g_flags[1], 1u);
    chunk = __shfl_sync(0xffffffffu, chunk, 0);

    while (chunk < NCHUNK) {
        unsigned next_raw = 0;
        if (lane == 0) next_raw = atomicAdd(&g_flags[1], 1u);

        #pragma unroll 1
        for (int g = 0; g < 4; g++) {
            const int e0 = (int)chunk * 16 + g * 4;

            int srcs[4], dsts[4];
            if (idx64) {
                #pragma unroll
                for (int n = 0; n < 4; n++) {
                    srcs[n] = (int)__ldg(&p64[e0 + n]);
                    dsts[n] = (int)__ldg(&p64[N_EDGES + e0 + n]);
                }
            } else {
                #pragma unroll
                for (int n = 0; n < 4; n++) {
                    srcs[n] = __ldg(&p32[e0 + n]);
                    dsts[n] = __ldg(&p32[N_EDGES + e0 + n]);
                }
            }

            // group 0: edge attrs (streaming, evict-first L2)
            #pragma unroll
            for (int m = 0; m < 2; m++) {
                const float* ga = &edge_attr[(size_t)(e0 + 2 * m + lh) * 64 + l16 * 4];
                cp_async16_stream(ea_smem + (uint32_t)((2 * m + lh) * EA_STRIDE + l16 * 4) * 4u, ga);
            }
            cp_commit();

            // group 1: K/Q (4x cp16) + V (2x cp16), covered by GEMM
            #pragma unroll
            for (int n = 0; n < 4; n++) {
                const float* s = (lh == 0)
                    ? &g_Kh[(size_t)srcs[n] * 64 + l16 * 4]
                    : &g_Qh[(size_t)dsts[n] * 64 + l16 * 4];
                cp_async16(kqv_smem + (uint32_t)(n * KQV_STRIDE + lh * 64 + l16 * 4) * 4u, s);
            }
            #pragma unroll
            for (int m = 0; m < 2; m++) {
                int sv = (lh == 0) ? srcs[2 * m] : srcs[2 * m + 1];
                const float* s = &g_Vh[(size_t)sv * 64 + l16 * 4];
                cp_async16(kqv_smem + (uint32_t)((2 * m + lh) * KQV_STRIDE + 128 + l16 * 4) * 4u, s);
            }
            cp_commit();

            cp_wait1();
            __syncwarp();

            // GEMM: 4 edges x 4 cols, FFMA2 (even-k, odd-k) lanes
            unsigned long long acc[4][4];
            #pragma unroll
            for (int e = 0; e < 4; e++) {
                acc[e][0] = bini0; acc[e][1] = bini1;
                acc[e][2] = bini2; acc[e][3] = bini3;
            }

            #pragma unroll 4
            for (int k4 = 0; k4 < 64; k4 += 4) {
                ulonglong2 ww0 = *reinterpret_cast<const ulonglong2*>(wrow0 + k4);
                ulonglong2 ww1 = *reinterpret_cast<const ulonglong2*>(wrow1 + k4);
                ulonglong2 ww2 = *reinterpret_cast<const ulonglong2*>(wrow2 + k4);
                ulonglong2 ww3 = *reinterpret_cast<const ulonglong2*>(wrow3 + k4);
                #pragma unroll
                for (int e = 0; e < 4; e++) {
                    ulonglong2 aa = *reinterpret_cast<const ulonglong2*>(
                        &sEA[(e_loc0 + e) * EA_STRIDE + k4]);
                    ffma2(acc[e][0], aa.x, ww0.x); ffma2(acc[e][0], aa.y, ww0.y);
                    ffma2(acc[e][1], aa.x, ww1.x); ffma2(acc[e][1], aa.y, ww1.y);
                    ffma2(acc[e][2], aa.x, ww2.x); ffma2(acc[e][2], aa.y, ww2.y);
                    ffma2(acc[e][3], aa.x, ww3.x); ffma2(acc[e][3], aa.y, ww3.y);
                }
            }

            cp_wait0();
            __syncwarp();

            // phase B: scores (stcs + smem stash), per-head exp, den red
            #pragma unroll
            for (int n = 0; n < 4; n++) {
                int e = e0 + n;
                int dst = dsts[n];
                const float* kqv = &sKQV[(e_loc0 + n) * KQV_STRIDE];
                float ew0 = sum2(acc[n][0]);
                float eb0 = sum2(acc[n][1]);
                float ew1 = sum2(acc[n][2]);
                float eb1 = sum2(acc[n][3]);

                float kq0 = kqv[lane]      + kqv[lane + 64];
                float kq1 = kqv[lane + 32] + kqv[lane + 96];
                float sc0 = signed_sqrt(kq0 * ew0) + eb0;
                float sc1 = signed_sqrt(kq1 * ew1) + eb1;

                __stcs(&wE_out[(size_t)e * 64 + lane],      sc0);
                __stcs(&wE_out[(size_t)e * 64 + lane + 32], sc1);
                float* srow = &sEA[(e_loc0 + n) * EA_STRIDE];
                srow[lane]      = sc0;
                srow[lane + 32] = sc1;

                float p0 = sc0 * aw0;
                float p1 = sc1 * aw1;
                #pragma unroll
                for (int off = 4; off > 0; off >>= 1) {
                    p0 += __shfl_xor_sync(0xffffffffu, p0, off);
                    p1 += __shfl_xor_sync(0xffffffffu, p1, off);
                }
                p0 = __expf(fminf(fmaxf(p0, -CLAMP_V), CLAMP_V));
                p1 = __expf(fminf(fmaxf(p1, -CLAMP_V), CLAMP_V));
                if (d0 == 0) {
                    sP[warp][n][h0]     = p0;
                    sP[warp][n][h0 + 4] = p1;
                    redAdd1(&g_den[(size_t)dst * 8 + h0],     p0);
                    redAdd1(&g_den[(size_t)dst * 8 + h0 + 4], p1);
                }
            }
            __syncwarp();

            // phase C: numerator scatter (all operands in smem)
            const int q  = lane & 15;
            const int j0 = q * 4;
            const int hq = q >> 1;
            #pragma unroll
            for (int n = 0; n < 4; n++) {
                float p = sP[warp][n][hq];
                int dst = dsts[n];
                if (lane < 16) {
                    float4 v = *reinterpret_cast<const float4*>(
                        &sKQV[(e_loc0 + n) * KQV_STRIDE + 128 + j0]);
                    redAddV4(&g_wV[(size_t)dst * 64 + j0], v.x * p, v.y * p, v.z * p, v.w * p);
                } else {
                    float4 et = *reinterpret_cast<const float4*>(
                        &sEA[(e_loc0 + n) * EA_STRIDE + j0]);
                    redAddV4(&g_rowV[(size_t)dst * 64 + j0], et.x * p, et.y * p, et.z * p, et.w * p);
                }
            }
            __syncwarp();
        }

        chunk = __shfl_sync(0xffffffffu, next_raw, 0);   // atomic long since done
    }
}

// ---------------- kernel 3: finalize (8 outputs per thread) ----------------
__global__ void k_final(const float* __restrict__ VeRow, float* __restrict__ wV_out) {
    __shared__ float sV[512];
    for (int i = threadIdx.x; i < 512; i += 256) sV[i] = VeRow[i];
    __syncthreads();

    int i = blockIdx.x * blockDim.x + threadIdx.x;
    if (i >= N_NODES * HEADS) return;
    int n = i >> 3, h = i & 7;
    float inv = 1.0f / (g_den[i] + 1e-16f);

    const float* rvp = &g_rowV[(size_t)n * 64 + h * 8];
    float4 rv0 = *reinterpret_cast<const float4*>(rvp);
    float4 rv1 = *reinterpret_cast<const float4*>(rvp + 4);
    float rv[8] = { rv0.x, rv0.y, rv0.z, rv0.w, rv1.x, rv1.y, rv1.z, rv1.w };

    const float* wvp = &g_wV[(size_t)n * 64 + h * 8];
    float4 wv0 = *reinterpret_cast<const float4*>(wvp);
    float4 wv1 = *reinterpret_cast<const float4*>(wvp + 4);
    float acc[8] = { wv0.x, wv0.y, wv0.z, wv0.w, wv1.x, wv1.y, wv1.z, wv1.w };

    #pragma unroll
    for (int d = 0; d < 8; d++) {
        float r = rv[d];
        const float* vc = &sV[d * 64 + h * 8];
        #pragma unroll
        for (int c = 0; c < 8; c++)
            acc[c] = fmaf(r, vc[c], acc[c]);
    }
    float* op = &wV_out[(size_t)n * 64 + h * 8];
    *reinterpret_cast<float4*>(op)     = make_float4(acc[0]*inv, acc[1]*inv, acc[2]*inv, acc[3]*inv);
    *reinterpret_cast<float4*>(op + 4) = make_float4(acc[4]*inv, acc[5]*inv, acc[6]*inv, acc[7]*inv);
}

// ---------------- launch ----------------
extern "C" void kernel_launch(void* const* d_in, const int* in_sizes, int n_in,
                              void* d_out, int out_size) {
    const float* x         = (const float*)d_in[0];
    const float* edge_attr = (const float*)d_in[1];
    const void*  ei_raw    = d_in[2];
    const float* Wq = (const float*)d_in[3];
    const float* bq = (const float*)d_in[4];
    const float* Wk = (const float*)d_in[5];
    const float* bk = (const float*)d_in[6];
    const float* We = (const float*)d_in[7];
    const float* be = (const float*)d_in[8];
    const float* Wv = (const float*)d_in[9];
    const float* bv = (const float*)d_in[10];
    const float* Aw = (const float*)d_in[11];
    const float* VeRow = (const float*)d_in[12];

    float* out    = (float*)d_out;
    float* wV_out = out;
    float* wE_out = out + (size_t)N_NODES * HDIM;

    cudaFuncSetAttribute(k_edge, cudaFuncAttributeMaxDynamicSharedMemorySize,
                         SMEM_EDGE_BYTES);

    void* flags_ptr = nullptr;
    cudaGetSymbolAddress(&flags_ptr, g_flags);
    cudaMemsetAsync(flags_ptr, 0, 2 * sizeof(unsigned));

    dim3 npgrid((N_NODES + 31) / 32, 3);
    k_nodeproj<<<npgrid, 256>>>(x, Wq, bq, Wk, bk, Wv, bv, (const unsigned*)ei_raw);
    k_edge<<<EDGE_GRID, 256, SMEM_EDGE_BYTES>>>(edge_attr, ei_raw, We, be, Aw, wE_out);
    k_final<<<(N_NODES * HEADS + 255) / 256, 256>>>(VeRow, wV_out);
}

// round 16
// speedup vs baseline: 1.2211x; 1.0029x over previous
#include <cuda_runtime.h>
#include <math.h>
#include <stdint.h>

#define N_NODES 50000
#define N_EDGES 800000
#define HEADS   8
#define ODIM    8
#define HDIM    64
#define CLAMP_V 5.0f
#define EPS_V   1e-8f
#define SQRT_EPS 9.9999997e-05f     // fp32 sqrt(1e-8)
#define EDGE_GRID 444               // 148 SMs * 3 persistent blocks
#define NCHUNK  (N_EDGES / 16)      // 50000 16-edge work units

#define W_STRIDE   68               // smem row stride in floats (272B, 16B-aligned)
#define EA_STRIDE  68               // sEA row stride (attrs, then scores)
#define KQV_STRIDE 192              // per-edge: K(64) Q(64) V(64)
#define SMEM_WT_FLOATS  (128 * W_STRIDE)     // 8704
#define SMEM_EA_FLOATS  (32 * EA_STRIDE)     // 2176
#define SMEM_KQV_FLOATS (32 * KQV_STRIDE)    // 6144
#define SMEM_EDGE_BYTES ((SMEM_WT_FLOATS + SMEM_EA_FLOATS + SMEM_KQV_FLOATS) * 4) // 68096

#define NP_BLOCKS 782               // ceil(50000/64) node blocks per plane

// ---------------- device scratch ----------------
__device__ __align__(16) float g_Qh[N_NODES * HDIM];
__device__ __align__(16) float g_Kh[N_NODES * HDIM];
__device__ __align__(16) float g_Vh[N_NODES * HDIM];
__device__ __align__(16) float g_den[N_NODES * HEADS];
__device__ __align__(16) float g_wV  [N_NODES * HDIM];
__device__ __align__(16) float g_rowV[N_NODES * HDIM];
__device__ __align__(8) unsigned g_flags[2];   // [0]=orhigh, [1]=work counter

// ---------------- helpers ----------------
__device__ __forceinline__ void redAddV4(float* p, float a, float b, float c, float d) {
    asm volatile("red.global.add.v4.f32 [%0], {%1,%2,%3,%4};"
                 :: "l"(p), "f"(a), "f"(b), "f"(c), "f"(d) : "memory");
}
__device__ __forceinline__ void redAdd1(float* p, float v) {
    asm volatile("red.global.add.f32 [%0], %1;" :: "l"(p), "f"(v) : "memory");
}
__device__ __forceinline__ void ffma2(unsigned long long& acc,
                                      unsigned long long a, unsigned long long b) {
    asm("fma.rn.f32x2 %0, %1, %2, %0;" : "+l"(acc) : "l"(a), "l"(b));
}
__device__ __forceinline__ unsigned long long pack2(float lo, float hi) {
    unsigned long long r;
    asm("mov.b64 %0, {%1,%2};" : "=l"(r) : "f"(lo), "f"(hi));
    return r;
}
__device__ __forceinline__ float sum2(unsigned long long v) {
    float2 r;
    asm("mov.b64 {%0,%1}, %2;" : "=f"(r.x), "=f"(r.y) : "l"(v));
    return r.x + r.y;
}
__device__ __forceinline__ float fsqrt_ap(float x) {
    float r; asm("sqrt.approx.f32 %0, %1;" : "=f"(r) : "f"(x)); return r;
}
// sqrt(relu(x)+eps) - sqrt(relu(-x)+eps) == copysign(sqrt(|x|+eps)-sqrt(eps), x)
__device__ __forceinline__ float signed_sqrt(float x) {
    float t = fsqrt_ap(fabsf(x) + EPS_V) - SQRT_EPS;
    return copysignf(t, x);
}
__device__ __forceinline__ void cp_async16(uint32_t smem_addr, const void* gptr) {
    asm volatile("cp.async.cg.shared.global [%0], [%1], 16;"
                 :: "r"(smem_addr), "l"(gptr));
}
// evict-first L2 policy for the big streaming edge_attr reads
__device__ __forceinline__ void cp_async16_stream(uint32_t smem_addr, const void* gptr) {
    asm volatile(
        "{\n\t"
        ".reg .b64 pol;\n\t"
        "createpolicy.fractional.L2::evict_first.b64 pol, 1.0;\n\t"
        "cp.async.cg.shared.global.L2::cache_hint [%0], [%1], 16, pol;\n\t"
        "}"
        :: "r"(smem_addr), "l"(gptr));
}
__device__ __forceinline__ void cp_commit() {
    asm volatile("cp.async.commit_group;" ::: "memory");
}
__device__ __forceinline__ void cp_wait1() {
    asm volatile("cp.async.wait_group 1;" ::: "memory");
}
__device__ __forceinline__ void cp_wait0() {
    asm volatile("cp.async.wait_group 0;" ::: "memory");
}

// ---------------- kernel 1: node projections (FFMA2) + init + dtype detect --
// grid (NP_BLOCKS, 3): y selects the projection; 64 nodes/block (8/warp).
// Lane owns output cols (lane, lane+32); FFMA2 lanes = (even-k, odd-k).
// Init/detect work is grid-strided over all 600k threads (<=2 iters each);
// the index high-word probes issue at kernel top, OR-reduced at kernel end.
__global__ void k_nodeproj(const float* __restrict__ x,
                           const float* __restrict__ Wq, const float* __restrict__ bq,
                           const float* __restrict__ Wk, const float* __restrict__ bk,
                           const float* __restrict__ Wv, const float* __restrict__ bv,
                           const unsigned* __restrict__ raw) {
    __shared__ float sWT[64 * W_STRIDE];       // transposed weights [c][k]  17408B
    __shared__ float sA[8][8][W_STRIDE];       // [warp][node][k]            17408B

    const int tid = threadIdx.x, warp = tid >> 5, lane = tid & 31;
    const int n0 = (blockIdx.x * 8 + warp) * 8;

    // ---- init + detect (grid-stride over both planes' flat ids) ----
    const int flat0 = (blockIdx.y * gridDim.x + blockIdx.x) * 256 + tid;
    const int gstride = gridDim.x * 3 * 256;
    unsigned hi = 0u;
    #pragma unroll 2
    for (int j = flat0; j < N_EDGES; j += gstride) {
        hi |= __ldg(&raw[2 * j + 1]);
        float4 z = make_float4(0.f, 0.f, 0.f, 0.f);
        reinterpret_cast<float4*>(g_wV)[j] = z;       // N_EDGES == N_NODES*HDIM/4
        reinterpret_cast<float4*>(g_rowV)[j] = z;
        if (j < N_NODES * HEADS / 4) reinterpret_cast<float4*>(g_den)[j] = z;
    }

    const float* W; const float* B; float* OUT;
    if (blockIdx.y == 0)      { W = Wq; B = bq; OUT = g_Qh; }
    else if (blockIdx.y == 1) { W = Wk; B = bk; OUT = g_Kh; }
    else                      { W = Wv; B = bv; OUT = g_Vh; }

    // transpose W into sWT
    for (int i = tid; i < 64 * 64; i += 256) {
        int k = i >> 6, c = i & 63;
        sWT[c * W_STRIDE + k] = W[i];
    }
    // load 8 node rows per warp (k-contiguous)
    #pragma unroll
    for (int n = 0; n < 8; n++) {
        int node = n0 + n; if (node >= N_NODES) node = N_NODES - 1;
        sA[warp][n][lane]      = x[(size_t)node * 64 + lane];
        sA[warp][n][lane + 32] = x[(size_t)node * 64 + lane + 32];
    }
    __syncthreads();

    const unsigned long long b0 = pack2(B[lane],      0.f);
    const unsigned long long b1 = pack2(B[lane + 32], 0.f);
    const float* wr0 = &sWT[lane * W_STRIDE];
    const float* wr1 = &sWT[(lane + 32) * W_STRIDE];

    unsigned long long acc[8][2];
    #pragma unroll
    for (int n = 0; n < 8; n++) { acc[n][0] = b0; acc[n][1] = b1; }

    #pragma unroll 4
    for (int k4 = 0; k4 < 64; k4 += 4) {
        ulonglong2 ww0 = *reinterpret_cast<const ulonglong2*>(wr0 + k4);
        ulonglong2 ww1 = *reinterpret_cast<const ulonglong2*>(wr1 + k4);
        #pragma unroll
        for (int n = 0; n < 8; n++) {
            ulonglong2 aa = *reinterpret_cast<const ulonglong2*>(&sA[warp][n][k4]);
            ffma2(acc[n][0], aa.x, ww0.x); ffma2(acc[n][0], aa.y, ww0.y);
            ffma2(acc[n][1], aa.x, ww1.x); ffma2(acc[n][1], aa.y, ww1.y);
        }
    }

    #pragma unroll
    for (int n = 0; n < 8; n++) {
        int node = n0 + n;
        if (node < N_NODES) {
            OUT[(size_t)node * 64 + lane]      = sum2(acc[n][0]);
            OUT[(size_t)node * 64 + lane + 32] = sum2(acc[n][1]);
        }
    }

    // ---- finish dtype detect ----
    hi = __reduce_or_sync(0xffffffffu, hi);
    if (lane == 0 && hi) atomicOr(&g_flags[0], hi);
}

// ---------------- kernel 2: fused edge kernel (dynamic warp scheduler) ------
// Warps grab 16-edge chunks via atomicAdd(g_flags[1]); next chunk's atomic is
// issued at chunk start, consumed at chunk end. Body identical to 475.9 run.
__global__ void __launch_bounds__(256, 3)
k_edge(const float* __restrict__ edge_attr,
       const void* __restrict__ ei_raw,
       const float* __restrict__ We, const float* __restrict__ be,
       const float* __restrict__ Aw,
       float* __restrict__ wE_out) {
    extern __shared__ float smem[];
    float* sWT  = smem;                                   // [128][W_STRIDE]
    float* sEA  = smem + SMEM_WT_FLOATS;                  // [32][EA_STRIDE]
    float* sKQV = smem + SMEM_WT_FLOATS + SMEM_EA_FLOATS; // [32][KQV_STRIDE]
    __shared__ float sP[8][4][8];                         // exp(s) [warp][edge][head]

    const int tid = threadIdx.x, warp = tid >> 5, lane = tid & 31;
    const int e_loc0 = warp * 4;

    for (int i = tid; i < 128 * 64; i += 256) {
        int c = i & 127, k = i >> 7;
        sWT[c * W_STRIDE + k] = We[k * 128 + c];
    }
    __syncthreads();

    const int d0 = lane & 7, h0 = lane >> 3;
    const int cw = (h0 << 4) + d0;
    const float aw0 = Aw[d0 * 8 + h0];
    const float aw1 = Aw[d0 * 8 + h0 + 4];

    const unsigned long long bini0 = pack2(be[cw],      0.f);
    const unsigned long long bini1 = pack2(be[cw + 8],  0.f);
    const unsigned long long bini2 = pack2(be[cw + 64], 0.f);
    const unsigned long long bini3 = pack2(be[cw + 72], 0.f);

    const float* wrow0 = &sWT[(cw)      * W_STRIDE];
    const float* wrow1 = &sWT[(cw + 8)  * W_STRIDE];
    const float* wrow2 = &sWT[(cw + 64) * W_STRIDE];
    const float* wrow3 = &sWT[(cw + 72) * W_STRIDE];

    const bool idx64 = (g_flags[0] == 0u);
    const long long* p64 = (const long long*)ei_raw;
    const int*       p32 = (const int*)ei_raw;

    const int l16 = lane & 15, lh = lane >> 4;

    const uint32_t ea_smem = (uint32_t)__cvta_generic_to_shared(
        &sEA[e_loc0 * EA_STRIDE]);
    const uint32_t kqv_smem = (uint32_t)__cvta_generic_to_shared(
        &sKQV[e_loc0 * KQV_STRIDE]);

    unsigned chunk = 0;
    if (lane == 0) chunk = atomicAdd(&g_flags[1], 1u);
    chunk = __shfl_sync(0xffffffffu, chunk, 0);

    while (chunk < NCHUNK) {
        unsigned next_raw = 0;
        if (lane == 0) next_raw = atomicAdd(&g_flags[1], 1u);

        #pragma unroll 1
        for (int g = 0; g < 4; g++) {
            const int e0 = (int)chunk * 16 + g * 4;

            int srcs[4], dsts[4];
            if (idx64) {
                #pragma unroll
                for (int n = 0; n < 4; n++) {
                    srcs[n] = (int)__ldg(&p64[e0 + n]);
                    dsts[n] = (int)__ldg(&p64[N_EDGES + e0 + n]);
                }
            } else {
                #pragma unroll
                for (int n = 0; n < 4; n++) {
                    srcs[n] = __ldg(&p32[e0 + n]);
                    dsts[n] = __ldg(&p32[N_EDGES + e0 + n]);
                }
            }

            // group 0: edge attrs (streaming, evict-first L2)
            #pragma unroll
            for (int m = 0; m < 2; m++) {
                const float* ga = &edge_attr[(size_t)(e0 + 2 * m + lh) * 64 + l16 * 4];
                cp_async16_stream(ea_smem + (uint32_t)((2 * m + lh) * EA_STRIDE + l16 * 4) * 4u, ga);
            }
            cp_commit();

            // group 1: K/Q (4x cp16) + V (2x cp16), covered by GEMM
            #pragma unroll
            for (int n = 0; n < 4; n++) {
                const float* s = (lh == 0)
                    ? &g_Kh[(size_t)srcs[n] * 64 + l16 * 4]
                    : &g_Qh[(size_t)dsts[n] * 64 + l16 * 4];
                cp_async16(kqv_smem + (uint32_t)(n * KQV_STRIDE + lh * 64 + l16 * 4) * 4u, s);
            }
            #pragma unroll
            for (int m = 0; m < 2; m++) {
                int sv = (lh == 0) ? srcs[2 * m] : srcs[2 * m + 1];
                const float* s = &g_Vh[(size_t)sv * 64 + l16 * 4];
                cp_async16(kqv_smem + (uint32_t)((2 * m + lh) * KQV_STRIDE + 128 + l16 * 4) * 4u, s);
            }
            cp_commit();

            cp_wait1();
            __syncwarp();

            // GEMM: 4 edges x 4 cols, FFMA2 (even-k, odd-k) lanes
            unsigned long long acc[4][4];
            #pragma unroll
            for (int e = 0; e < 4; e++) {
                acc[e][0] = bini0; acc[e][1] = bini1;
                acc[e][2] = bini2; acc[e][3] = bini3;
            }

            #pragma unroll 4
            for (int k4 = 0; k4 < 64; k4 += 4) {
                ulonglong2 ww0 = *reinterpret_cast<const ulonglong2*>(wrow0 + k4);
                ulonglong2 ww1 = *reinterpret_cast<const ulonglong2*>(wrow1 + k4);
                ulonglong2 ww2 = *reinterpret_cast<const ulonglong2*>(wrow2 + k4);
                ulonglong2 ww3 = *reinterpret_cast<const ulonglong2*>(wrow3 + k4);
                #pragma unroll
                for (int e = 0; e < 4; e++) {
                    ulonglong2 aa = *reinterpret_cast<const ulonglong2*>(
                        &sEA[(e_loc0 + e) * EA_STRIDE + k4]);
                    ffma2(acc[e][0], aa.x, ww0.x); ffma2(acc[e][0], aa.y, ww0.y);
                    ffma2(acc[e][1], aa.x, ww1.x); ffma2(acc[e][1], aa.y, ww1.y);
                    ffma2(acc[e][2], aa.x, ww2.x); ffma2(acc[e][2], aa.y, ww2.y);
                    ffma2(acc[e][3], aa.x, ww3.x); ffma2(acc[e][3], aa.y, ww3.y);
                }
            }

            cp_wait0();
            __syncwarp();

            // phase B: scores (stcs + smem stash), per-head exp, den red
            #pragma unroll
            for (int n = 0; n < 4; n++) {
                int e = e0 + n;
                int dst = dsts[n];
                const float* kqv = &sKQV[(e_loc0 + n) * KQV_STRIDE];
                float ew0 = sum2(acc[n][0]);
                float eb0 = sum2(acc[n][1]);
                float ew1 = sum2(acc[n][2]);
                float eb1 = sum2(acc[n][3]);

                float kq0 = kqv[lane]      + kqv[lane + 64];
                float kq1 = kqv[lane + 32] + kqv[lane + 96];
                float sc0 = signed_sqrt(kq0 * ew0) + eb0;
                float sc1 = signed_sqrt(kq1 * ew1) + eb1;

                __stcs(&wE_out[(size_t)e * 64 + lane],      sc0);
                __stcs(&wE_out[(size_t)e * 64 + lane + 32], sc1);
                float* srow = &sEA[(e_loc0 + n) * EA_STRIDE];
                srow[lane]      = sc0;
                srow[lane + 32] = sc1;

                float p0 = sc0 * aw0;
                float p1 = sc1 * aw1;
                #pragma unroll
                for (int off = 4; off > 0; off >>= 1) {
                    p0 += __shfl_xor_sync(0xffffffffu, p0, off);
                    p1 += __shfl_xor_sync(0xffffffffu, p1, off);
                }
                p0 = __expf(fminf(fmaxf(p0, -CLAMP_V), CLAMP_V));
                p1 = __expf(fminf(fmaxf(p1, -CLAMP_V), CLAMP_V));
                if (d0 == 0) {
                    sP[warp][n][h0]     = p0;
                    sP[warp][n][h0 + 4] = p1;
                    redAdd1(&g_den[(size_t)dst * 8 + h0],     p0);
                    redAdd1(&g_den[(size_t)dst * 8 + h0 + 4], p1);
                }
            }
            __syncwarp();

            // phase C: numerator scatter (all operands in smem)
            const int q  = lane & 15;
            const int j0 = q * 4;
            const int hq = q >> 1;
            #pragma unroll
            for (int n = 0; n < 4; n++) {
                float p = sP[warp][n][hq];
                int dst = dsts[n];
                if (lane < 16) {
                    float4 v = *reinterpret_cast<const float4*>(
                        &sKQV[(e_loc0 + n) * KQV_STRIDE + 128 + j0]);
                    redAddV4(&g_wV[(size_t)dst * 64 + j0], v.x * p, v.y * p, v.z * p, v.w * p);
                } else {
                    float4 et = *reinterpret_cast<const float4*>(
                        &sEA[(e_loc0 + n) * EA_STRIDE + j0]);
                    redAddV4(&g_rowV[(size_t)dst * 64 + j0], et.x * p, et.y * p, et.z * p, et.w * p);
                }
            }
            __syncwarp();
        }

        chunk = __shfl_sync(0xffffffffu, next_raw, 0);   // atomic long since done
    }
}

// ---------------- kernel 3: finalize (8 outputs per thread) ----------------
__global__ void k_final(const float* __restrict__ VeRow, float* __restrict__ wV_out) {
    __shared__ float sV[512];
    for (int i = threadIdx.x; i < 512; i += 256) sV[i] = VeRow[i];
    __syncthreads();

    int i = blockIdx.x * blockDim.x + threadIdx.x;
    if (i >= N_NODES * HEADS) return;
    int n = i >> 3, h = i & 7;
    float inv = 1.0f / (g_den[i] + 1e-16f);

    const float* rvp = &g_rowV[(size_t)n * 64 + h * 8];
    float4 rv0 = *reinterpret_cast<const float4*>(rvp);
    float4 rv1 = *reinterpret_cast<const float4*>(rvp + 4);
    float rv[8] = { rv0.x, rv0.y, rv0.z, rv0.w, rv1.x, rv1.y, rv1.z, rv1.w };

    const float* wvp = &g_wV[(size_t)n * 64 + h * 8];
    float4 wv0 = *reinterpret_cast<const float4*>(wvp);
    float4 wv1 = *reinterpret_cast<const float4*>(wvp + 4);
    float acc[8] = { wv0.x, wv0.y, wv0.z, wv0.w, wv1.x, wv1.y, wv1.z, wv1.w };

    #pragma unroll
    for (int d = 0; d < 8; d++) {
        float r = rv[d];
        const float* vc = &sV[d * 64 + h * 8];
        #pragma unroll
        for (int c = 0; c < 8; c++)
            acc[c] = fmaf(r, vc[c], acc[c]);
    }
    float* op = &wV_out[(size_t)n * 64 + h * 8];
    *reinterpret_cast<float4*>(op)     = make_float4(acc[0]*inv, acc[1]*inv, acc[2]*inv, acc[3]*inv);
    *reinterpret_cast<float4*>(op + 4) = make_float4(acc[4]*inv, acc[5]*inv, acc[6]*inv, acc[7]*inv);
}

// ---------------- launch ----------------
extern "C" void kernel_launch(void* const* d_in, const int* in_sizes, int n_in,
                              void* d_out, int out_size) {
    const float* x         = (const float*)d_in[0];
    const float* edge_attr = (const float*)d_in[1];
    const void*  ei_raw    = d_in[2];
    const float* Wq = (const float*)d_in[3];
    const float* bq = (const float*)d_in[4];
    const float* Wk = (const float*)d_in[5];
    const float* bk = (const float*)d_in[6];
    const float* We = (const float*)d_in[7];
    const float* be = (const float*)d_in[8];
    const float* Wv = (const float*)d_in[9];
    const float* bv = (const float*)d_in[10];
    const float* Aw = (const float*)d_in[11];
    const float* VeRow = (const float*)d_in[12];

    float* out    = (float*)d_out;
    float* wV_out = out;
    float* wE_out = out + (size_t)N_NODES * HDIM;

    cudaFuncSetAttribute(k_edge, cudaFuncAttributeMaxDynamicSharedMemorySize,
                         SMEM_EDGE_BYTES);

    void* flags_ptr = nullptr;
    cudaGetSymbolAddress(&flags_ptr, g_flags);
    cudaMemsetAsync(flags_ptr, 0, 2 * sizeof(unsigned));

    dim3 npgrid(NP_BLOCKS, 3);
    k_nodeproj<<<npgrid, 256>>>(x, Wq, bq, Wk, bk, Wv, bv, (const unsigned*)ei_raw);
    k_edge<<<EDGE_GRID, 256, SMEM_EDGE_BYTES>>>(edge_attr, ei_raw, We, be, Aw, wE_out);
    k_final<<<(N_NODES * HEADS + 255) / 256, 256>>>(VeRow, wV_out);
}